// round 5
// baseline (speedup 1.0000x reference)
#include <cuda_runtime.h>
#include <cstdint>

// ---------------------------------------------------------------------------
// SwinBlock: B=32, H=W=56, C=192, heads=6, head_dim=32, WS=7, SS=3, N=49
// tf32 mma.sync GEMMs, 128x192 CTA tile, 3-stage cp.async, fused LN2.
// ---------------------------------------------------------------------------

#define HW      56
#define Cdim    192
#define NHEADS  6
#define HDIM    32
#define WSZ     7
#define SSH     3
#define NTOK    49
#define NWIN    2048
#define MROWS   100352
#define HID     768
#define SCALE   0.17677669529663687f

// -------------------------- scratch (device globals) -----------------------
__device__ __align__(16) float g_win  [(size_t)MROWS * Cdim];
__device__ __align__(16) float g_qkv  [(size_t)MROWS * 3 * Cdim];
__device__ __align__(16) float g_attno[(size_t)MROWS * Cdim];
__device__ __align__(16) float g_h    [(size_t)MROWS * Cdim];
__device__ __align__(16) float g_ln2  [(size_t)MROWS * Cdim];
__device__ __align__(16) float g_hid  [(size_t)MROWS * HID];
__device__ __align__(16) float g_qkvwT[576 * 192];
__device__ __align__(16) float g_projwT[192 * 192];
__device__ __align__(16) float g_w1T  [HID * 192];
__device__ __align__(16) float g_w2T  [192 * HID];

// ------------------------------ helpers ------------------------------------
__device__ __forceinline__ float rn_tf32(float x) {
    float y;
    asm("cvt.rna.tf32.f32 %0, %1;" : "=f"(y) : "f"(x));
    return y;
}
__device__ __forceinline__ void cpasync16(float* dst, const float* src) {
    uint32_t d = (uint32_t)__cvta_generic_to_shared(dst);
    asm volatile("cp.async.cg.shared.global [%0], [%1], 16;" :: "r"(d), "l"(src));
}
#define CP_COMMIT() asm volatile("cp.async.commit_group;" ::: "memory")

__device__ __forceinline__ void mma_tf32(float* d, const float* a, const float* b) {
    asm volatile(
        "mma.sync.aligned.m16n8k8.row.col.f32.tf32.tf32.f32 "
        "{%0,%1,%2,%3}, {%4,%5,%6,%7}, {%8,%9}, {%0,%1,%2,%3};"
        : "+f"(d[0]), "+f"(d[1]), "+f"(d[2]), "+f"(d[3])
        : "r"(__float_as_uint(a[0])), "r"(__float_as_uint(a[1])),
          "r"(__float_as_uint(a[2])), "r"(__float_as_uint(a[3])),
          "r"(__float_as_uint(b[0])), "r"(__float_as_uint(b[1])));
}

__device__ __forceinline__ int permrow(int rw) {
    int win = rw / NTOK, n = rw - win * NTOK;
    int b   = win >> 6, wi = win & 63;
    int wh  = wi >> 3,  ww = wi & 7;
    int i   = n / WSZ,  j  = n - i * WSZ;
    int hs  = wh * WSZ + i + SSH; if (hs >= HW) hs -= HW;
    int ws  = ww * WSZ + j + SSH; if (ws >= HW) ws -= HW;
    return b * (HW * HW) + hs * HW + ws;
}

// ------------------------- weight transpose (+tf32 round) ------------------
__global__ void transpose_kernel(const float* __restrict__ in, float* __restrict__ out,
                                 int R, int C) {
    __shared__ float t[32][33];
    int bx = blockIdx.x * 32, by = blockIdx.y * 32;
    int x = threadIdx.x, y0 = threadIdx.y;
    #pragma unroll
    for (int j = 0; j < 32; j += 8)
        t[y0 + j][x] = in[(size_t)(by + y0 + j) * C + bx + x];
    __syncthreads();
    #pragma unroll
    for (int j = 0; j < 32; j += 8)
        out[(size_t)(bx + y0 + j) * R + by + x] = rn_tf32(t[x][y0 + j]);
}

// ------------------------------ LayerNorm (warp/row) -----------------------
__global__ __launch_bounds__(256)
void ln_kernel(const float* __restrict__ in, const float* __restrict__ gamma,
               const float* __restrict__ beta, float* __restrict__ out, int remap) {
    int wid = threadIdx.x >> 5, lane = threadIdx.x & 31;
    int row = blockIdx.x * 8 + wid;
    int src = remap ? permrow(row) : row;
    const float* p = in + (size_t)src * Cdim;

    float v[6];
    #pragma unroll
    for (int j = 0; j < 6; j++) v[j] = p[lane + 32 * j];
    float s = v[0] + v[1] + v[2] + v[3] + v[4] + v[5];
    #pragma unroll
    for (int o = 16; o; o >>= 1) s += __shfl_xor_sync(0xffffffffu, s, o);
    float mu = s * (1.0f / Cdim);
    float sq = 0.f;
    #pragma unroll
    for (int j = 0; j < 6; j++) { v[j] -= mu; sq += v[j] * v[j]; }
    #pragma unroll
    for (int o = 16; o; o >>= 1) sq += __shfl_xor_sync(0xffffffffu, sq, o);
    float inv = rsqrtf(sq * (1.0f / Cdim) + 1e-5f);
    float* q = out + (size_t)row * Cdim;
    #pragma unroll
    for (int j = 0; j < 6; j++) {
        int c = lane + 32 * j;
        q[c] = rn_tf32(v[j] * inv * gamma[c] + beta[c]);
    }
}

// --------------------------- tf32 mma.sync GEMM ----------------------------
// C[M,N] = A[M,K] @ BT[N,K]^T. CTA 128x192, 8 warps (2x4), warp 64x48.
// 3-stage cp.async pipeline. EPI: 0 plain, 1 GELU, 2 permrow+resid+fused LN2,
// 3 +resid.
#define AS_STRIDE 20
#define AS_BUF (128 * AS_STRIDE)        // 2560 floats
#define BS_BUF (192 * AS_STRIDE)        // 3840 floats
#define SM_AS  0
#define SM_BS  (3 * AS_BUF)             // 7680
#define SM_SUM (SM_BS + 3 * BS_BUF)     // 19200
#define SM_SQ  (SM_SUM + 512)           // 19712
#define SM_TOT ((SM_SQ + 512) * 4)      // 80896 bytes

__device__ __forceinline__ void gemm_load(const float* __restrict__ A,
                                          const float* __restrict__ BT,
                                          float* As, float* Bs,
                                          int mBase, int nBase, int K, int k0, int tid) {
    #pragma unroll
    for (int i = 0; i < 2; i++) {
        int idx = tid + i * 256;
        int r = idx >> 2, ch = idx & 3;
        cpasync16(As + r * AS_STRIDE + ch * 4,
                  A + (size_t)(mBase + r) * K + k0 + ch * 4);
    }
    #pragma unroll
    for (int i = 0; i < 3; i++) {
        int idx = tid + i * 256;
        int r = idx >> 2, ch = idx & 3;
        cpasync16(Bs + r * AS_STRIDE + ch * 4,
                  BT + (size_t)(nBase + r) * K + k0 + ch * 4);
    }
    CP_COMMIT();
}

template<int EPI>
__global__ __launch_bounds__(256)
void tc_gemm(const float* __restrict__ A, const float* __restrict__ BT,
             const float* __restrict__ bias, float* __restrict__ C,
             int N, int K, const float* __restrict__ resid,
             float* __restrict__ C2, const float* __restrict__ g2,
             const float* __restrict__ b2v) {
    extern __shared__ float sm[];
    float* AsBase = sm + SM_AS;
    float* BsBase = sm + SM_BS;

    int tid  = threadIdx.x;
    int wid  = tid >> 5, lane = tid & 31;
    int g    = lane >> 2, tig = lane & 3;
    int wm   = wid & 1, wn = wid >> 1;         // 2 x 4 warp grid
    int mBase = blockIdx.x * 128;
    int nBase = blockIdx.y * 192;
    int nk = K >> 4;

    float acc[4][6][4];
    #pragma unroll
    for (int mt = 0; mt < 4; mt++)
        #pragma unroll
        for (int nt = 0; nt < 6; nt++)
            #pragma unroll
            for (int e = 0; e < 4; e++) acc[mt][nt][e] = 0.f;

    // prologue: stages 0, 1
    gemm_load(A, BT, AsBase, BsBase, mBase, nBase, K, 0, tid);
    gemm_load(A, BT, AsBase + AS_BUF, BsBase + BS_BUF, mBase, nBase, K, 16, tid);

    for (int kt = 0; kt < nk; kt++) {
        if (kt + 1 < nk)
            asm volatile("cp.async.wait_group 1;" ::: "memory");
        else
            asm volatile("cp.async.wait_group 0;" ::: "memory");
        __syncthreads();

        if (kt + 2 < nk) {
            int nb = (kt + 2) % 3;
            gemm_load(A, BT, AsBase + nb * AS_BUF, BsBase + nb * BS_BUF,
                      mBase, nBase, K, (kt + 2) << 4, tid);
        }

        int buf = kt % 3;
        const float* As = AsBase + buf * AS_BUF;
        const float* Bs = BsBase + buf * BS_BUF;

        #pragma unroll
        for (int s = 0; s < 2; s++) {
            int kf = s * 8 + tig;
            float a[4][4], b[6][2];
            #pragma unroll
            for (int mt = 0; mt < 4; mt++) {
                int r = wm * 64 + mt * 16 + g;
                a[mt][0] = As[r * AS_STRIDE + kf];
                a[mt][1] = As[(r + 8) * AS_STRIDE + kf];
                a[mt][2] = As[r * AS_STRIDE + kf + 4];
                a[mt][3] = As[(r + 8) * AS_STRIDE + kf + 4];
            }
            #pragma unroll
            for (int nt = 0; nt < 6; nt++) {
                int n = wn * 48 + nt * 8 + g;
                b[nt][0] = Bs[n * AS_STRIDE + kf];
                b[nt][1] = Bs[n * AS_STRIDE + kf + 4];
            }
            #pragma unroll
            for (int mt = 0; mt < 4; mt++)
                #pragma unroll
                for (int nt = 0; nt < 6; nt++)
                    mma_tf32(acc[mt][nt], a[mt], b[nt]);
        }
        __syncthreads();
    }

    // ---------------- epilogue ----------------
    float* s_sum = sm + SM_SUM;   // [4 wn][128 row]
    float* s_sq  = sm + SM_SQ;

    if (EPI == 2) { /* zero not needed: each slot written exactly once */ }

    #pragma unroll
    for (int mt = 0; mt < 4; mt++) {
        int lr0 = wm * 64 + mt * 16 + g;
        int lr1 = lr0 + 8;
        int r0 = mBase + lr0, r1 = mBase + lr1;
        int p0 = r0, p1 = r1;
        if (EPI == 2) { p0 = permrow(r0); p1 = permrow(r1); }

        float s0 = 0.f, q0 = 0.f, s1 = 0.f, q1 = 0.f;
        #pragma unroll
        for (int nt = 0; nt < 6; nt++) {
            int c = nBase + wn * 48 + nt * 8 + 2 * tig;
            float2 bv = *(const float2*)(bias + c);
            float v0 = acc[mt][nt][0] + bv.x;
            float v1 = acc[mt][nt][1] + bv.y;
            float v2 = acc[mt][nt][2] + bv.x;
            float v3 = acc[mt][nt][3] + bv.y;
            if (EPI == 1) {
                v0 = rn_tf32(0.5f * v0 * (1.0f + erff(v0 * 0.70710678118654752f)));
                v1 = rn_tf32(0.5f * v1 * (1.0f + erff(v1 * 0.70710678118654752f)));
                v2 = rn_tf32(0.5f * v2 * (1.0f + erff(v2 * 0.70710678118654752f)));
                v3 = rn_tf32(0.5f * v3 * (1.0f + erff(v3 * 0.70710678118654752f)));
            } else if (EPI == 2) {
                float2 ra = *(const float2*)(resid + (size_t)p0 * Cdim + c);
                float2 rb = *(const float2*)(resid + (size_t)p1 * Cdim + c);
                v0 += ra.x; v1 += ra.y; v2 += rb.x; v3 += rb.y;
                s0 += v0 + v1; q0 += v0 * v0 + v1 * v1;
                s1 += v2 + v3; q1 += v2 * v2 + v3 * v3;
                acc[mt][nt][0] = v0; acc[mt][nt][1] = v1;
                acc[mt][nt][2] = v2; acc[mt][nt][3] = v3;
            } else if (EPI == 3) {
                float2 ra = *(const float2*)(resid + (size_t)r0 * Cdim + c);
                float2 rb = *(const float2*)(resid + (size_t)r1 * Cdim + c);
                v0 += ra.x; v1 += ra.y; v2 += rb.x; v3 += rb.y;
            }
            *(float2*)(C + (size_t)p0 * N + c) = make_float2(v0, v1);
            *(float2*)(C + (size_t)p1 * N + c) = make_float2(v2, v3);
        }
        if (EPI == 2) {
            // reduce over tig (4 consecutive lanes)
            #pragma unroll
            for (int o = 1; o < 4; o <<= 1) {
                s0 += __shfl_xor_sync(0xffffffffu, s0, o);
                q0 += __shfl_xor_sync(0xffffffffu, q0, o);
                s1 += __shfl_xor_sync(0xffffffffu, s1, o);
                q1 += __shfl_xor_sync(0xffffffffu, q1, o);
            }
            if (tig == 0) {
                s_sum[wn * 128 + lr0] = s0;  s_sq[wn * 128 + lr0] = q0;
                s_sum[wn * 128 + lr1] = s1;  s_sq[wn * 128 + lr1] = q1;
            }
        }
    }

    if (EPI == 2) {
        __syncthreads();
        #pragma unroll
        for (int mt = 0; mt < 4; mt++) {
            int lr0 = wm * 64 + mt * 16 + g;
            int lr1 = lr0 + 8;
            int p0 = permrow(mBase + lr0), p1 = permrow(mBase + lr1);
            float su0 = s_sum[lr0] + s_sum[128 + lr0] + s_sum[256 + lr0] + s_sum[384 + lr0];
            float sq0 = s_sq[lr0]  + s_sq[128 + lr0]  + s_sq[256 + lr0]  + s_sq[384 + lr0];
            float su1 = s_sum[lr1] + s_sum[128 + lr1] + s_sum[256 + lr1] + s_sum[384 + lr1];
            float sq1 = s_sq[lr1]  + s_sq[128 + lr1]  + s_sq[256 + lr1]  + s_sq[384 + lr1];
            float mu0 = su0 * (1.0f / Cdim);
            float mu1 = su1 * (1.0f / Cdim);
            float iv0 = rsqrtf(sq0 * (1.0f / Cdim) - mu0 * mu0 + 1e-5f);
            float iv1 = rsqrtf(sq1 * (1.0f / Cdim) - mu1 * mu1 + 1e-5f);
            #pragma unroll
            for (int nt = 0; nt < 6; nt++) {
                int c = wn * 48 + nt * 8 + 2 * tig;
                float2 gv = *(const float2*)(g2 + c);
                float2 bb = *(const float2*)(b2v + c);
                float o0 = rn_tf32((acc[mt][nt][0] - mu0) * iv0 * gv.x + bb.x);
                float o1 = rn_tf32((acc[mt][nt][1] - mu0) * iv0 * gv.y + bb.y);
                float o2 = rn_tf32((acc[mt][nt][2] - mu1) * iv1 * gv.x + bb.x);
                float o3 = rn_tf32((acc[mt][nt][3] - mu1) * iv1 * gv.y + bb.y);
                *(float2*)(C2 + (size_t)p0 * Cdim + c) = make_float2(o0, o1);
                *(float2*)(C2 + (size_t)p1 * Cdim + c) = make_float2(o2, o3);
            }
        }
    }
}

// ----------------------------- Attention -----------------------------------
__global__ __launch_bounds__(256)
void attn_kernel(const float* __restrict__ rpb_table) {
    __shared__ float qs[NTOK][HDIM];
    __shared__ float ks[NTOK][HDIM];
    __shared__ float vs[NTOK][HDIM];
    __shared__ float S[NTOK][NTOK];

    int win  = blockIdx.x / NHEADS;
    int head = blockIdx.x - win * NHEADS;
    int tid  = threadIdx.x;
    int wi = win & 63;
    int wh = wi >> 3, ww = wi & 7;

    const float* base = g_qkv + (size_t)win * NTOK * (3 * Cdim) + head * HDIM;

    for (int idx = tid; idx < NTOK * 8; idx += 256) {
        int n = idx >> 3, dg = idx & 7;
        const float4* r = (const float4*)(base + (size_t)n * (3 * Cdim));
        float4 q = r[dg];
        q.x *= SCALE; q.y *= SCALE; q.z *= SCALE; q.w *= SCALE;
        ((float4*)qs[n])[dg] = q;
        ((float4*)ks[n])[dg] = r[(Cdim / 4) + dg];
        ((float4*)vs[n])[dg] = r[(2 * Cdim / 4) + dg];
    }
    __syncthreads();

    for (int e = tid; e < NTOK * NTOK; e += 256) {
        int i = e / NTOK, j = e - i * NTOK;
        const float4* qp = (const float4*)qs[i];
        const float4* kp = (const float4*)ks[j];
        float dot = 0.f;
        #pragma unroll
        for (int d = 0; d < 8; d++) {
            float4 qv = qp[d], kv = kp[d];
            dot += qv.x * kv.x + qv.y * kv.y + qv.z * kv.z + qv.w * kv.w;
        }
        int ri = i / WSZ, ci = i - ri * WSZ;
        int rj = j / WSZ, cj = j - rj * WSZ;
        dot += rpb_table[((ri - rj + 6) * 13 + (ci - cj + 6)) * NHEADS + head];
        int hi = wh * WSZ + ri, wiC = ww * WSZ + ci;
        int hj = wh * WSZ + rj, wjC = ww * WSZ + cj;
        int gi = (hi < 49 ? 0 : (hi < 53 ? 1 : 2)) * 3 + (wiC < 49 ? 0 : (wiC < 53 ? 1 : 2));
        int gj = (hj < 49 ? 0 : (hj < 53 ? 1 : 2)) * 3 + (wjC < 49 ? 0 : (wjC < 53 ? 1 : 2));
        if (gi != gj) dot -= 100.0f;
        S[i][j] = dot;
    }
    __syncthreads();

    int warp = tid >> 5, lane = tid & 31;
    for (int r = warp; r < NTOK; r += 8) {
        float v0 = (lane < NTOK) ? S[r][lane] : -1e30f;
        float v1 = (lane + 32 < NTOK) ? S[r][lane + 32] : -1e30f;
        float m = fmaxf(v0, v1);
        #pragma unroll
        for (int o = 16; o; o >>= 1) m = fmaxf(m, __shfl_xor_sync(0xffffffffu, m, o));
        float e0 = (lane < NTOK) ? __expf(v0 - m) : 0.f;
        float e1 = (lane + 32 < NTOK) ? __expf(v1 - m) : 0.f;
        float s = e0 + e1;
        #pragma unroll
        for (int o = 16; o; o >>= 1) s += __shfl_xor_sync(0xffffffffu, s, o);
        float inv = __fdividef(1.0f, s);
        if (lane < NTOK)      S[r][lane]      = e0 * inv;
        if (lane + 32 < NTOK) S[r][lane + 32] = e1 * inv;
    }
    __syncthreads();

    for (int e = tid; e < NTOK * 8; e += 256) {
        int n = e >> 3, dg = e & 7;
        float4 acc = make_float4(0.f, 0.f, 0.f, 0.f);
        #pragma unroll 7
        for (int m = 0; m < NTOK; m++) {
            float s = S[n][m];
            float4 v = ((const float4*)vs[m])[dg];
            acc.x += s * v.x; acc.y += s * v.y; acc.z += s * v.z; acc.w += s * v.w;
        }
        acc.x = rn_tf32(acc.x); acc.y = rn_tf32(acc.y);
        acc.z = rn_tf32(acc.z); acc.w = rn_tf32(acc.w);
        *(float4*)&g_attno[(size_t)(win * NTOK + n) * Cdim + head * HDIM + dg * 4] = acc;
    }
}

// ------------------------------ launcher -----------------------------------
extern "C" void kernel_launch(void* const* d_in, const int* in_sizes, int n_in,
                              void* d_out, int out_size) {
    const float* x      = (const float*)d_in[0];
    const float* qkv_w  = (const float*)d_in[1];
    const float* qkv_b  = (const float*)d_in[2];
    const float* proj_w = (const float*)d_in[3];
    const float* proj_b = (const float*)d_in[4];
    const float* rpb    = (const float*)d_in[5];
    const float* ln1_g  = (const float*)d_in[6];
    const float* ln1_b  = (const float*)d_in[7];
    const float* ln2_g  = (const float*)d_in[8];
    const float* ln2_b  = (const float*)d_in[9];
    const float* w1     = (const float*)d_in[10];
    const float* b1     = (const float*)d_in[11];
    const float* w2     = (const float*)d_in[12];
    const float* b2     = (const float*)d_in[13];
    float* out = (float*)d_out;

    float *p_win, *p_qkv, *p_attno, *p_h, *p_ln2, *p_hid;
    float *p_qkvwT, *p_projwT, *p_w1T, *p_w2T;
    cudaGetSymbolAddress((void**)&p_win,    g_win);
    cudaGetSymbolAddress((void**)&p_qkv,    g_qkv);
    cudaGetSymbolAddress((void**)&p_attno,  g_attno);
    cudaGetSymbolAddress((void**)&p_h,      g_h);
    cudaGetSymbolAddress((void**)&p_ln2,    g_ln2);
    cudaGetSymbolAddress((void**)&p_hid,    g_hid);
    cudaGetSymbolAddress((void**)&p_qkvwT,  g_qkvwT);
    cudaGetSymbolAddress((void**)&p_projwT, g_projwT);
    cudaGetSymbolAddress((void**)&p_w1T,    g_w1T);
    cudaGetSymbolAddress((void**)&p_w2T,    g_w2T);

    static int smem_set = 0;
    if (!smem_set) {
        cudaFuncSetAttribute(tc_gemm<0>, cudaFuncAttributeMaxDynamicSharedMemorySize, SM_TOT);
        cudaFuncSetAttribute(tc_gemm<1>, cudaFuncAttributeMaxDynamicSharedMemorySize, SM_TOT);
        cudaFuncSetAttribute(tc_gemm<2>, cudaFuncAttributeMaxDynamicSharedMemorySize, SM_TOT);
        cudaFuncSetAttribute(tc_gemm<3>, cudaFuncAttributeMaxDynamicSharedMemorySize, SM_TOT);
        smem_set = 1;
    }

    dim3 tb(32, 8);
    transpose_kernel<<<dim3(576 / 32, 192 / 32), tb>>>(qkv_w,  p_qkvwT, 192, 576);
    transpose_kernel<<<dim3(192 / 32, 192 / 32), tb>>>(proj_w, p_projwT, 192, 192);
    transpose_kernel<<<dim3(HID / 32, 192 / 32), tb>>>(w1,     p_w1T,   192, HID);
    transpose_kernel<<<dim3(192 / 32, HID / 32), tb>>>(w2,     p_w2T,   HID, 192);

    // 1. LN1 + shifted-window partition
    ln_kernel<<<MROWS / 8, 256>>>(x, ln1_g, ln1_b, p_win, 1);

    // 2. QKV: (100352,192) @ (192,576)
    tc_gemm<0><<<dim3(MROWS / 128, 3), 256, SM_TOT>>>(
        p_win, p_qkvwT, qkv_b, p_qkv, 576, 192, nullptr, nullptr, nullptr, nullptr);

    // 3. windowed attention
    attn_kernel<<<NWIN * NHEADS, 256>>>(rpb);

    // 4. proj + window-reverse + residual(x) + fused LN2 (writes g_h AND g_ln2)
    tc_gemm<2><<<dim3(MROWS / 128, 1), 256, SM_TOT>>>(
        p_attno, p_projwT, proj_b, p_h, 192, 192, x, p_ln2, ln2_g, ln2_b);

    // 5. MLP1 + GELU
    tc_gemm<1><<<dim3(MROWS / 128, 4), 256, SM_TOT>>>(
        p_ln2, p_w1T, b1, p_hid, HID, 192, nullptr, nullptr, nullptr, nullptr);

    // 6. MLP2 + residual(h)
    tc_gemm<3><<<dim3(MROWS / 128, 1), 256, SM_TOT>>>(
        p_hid, p_w2T, b2, out, 192, HID, p_h, nullptr, nullptr, nullptr);
}

// round 6
// speedup vs baseline: 1.2408x; 1.2408x over previous
#include <cuda_runtime.h>
#include <cuda_bf16.h>
#include <cstdint>

// ---------------------------------------------------------------------------
// SwinBlock: B=32, H=W=56, C=192, heads=6, head_dim=32, WS=7, SS=3, N=49
// bf16 mma.sync GEMMs (fp32 accum), bf16 scratch, fused LN2 in proj.
// ---------------------------------------------------------------------------

#define HW      56
#define Cdim    192
#define NHEADS  6
#define HDIM    32
#define WSZ     7
#define SSH     3
#define NTOK    49
#define NWIN    2048
#define MROWS   100352
#define HID     768
#define SCALE   0.17677669529663687f
#define SROW    40      // bf16 elems per smem row (32 data + 8 pad)

typedef __nv_bfloat16 bf16;
typedef __nv_bfloat162 bf162;

// -------------------------- scratch (device globals) -----------------------
__device__ __align__(16) bf16  g_winb [(size_t)MROWS * Cdim];
__device__ __align__(16) bf16  g_qkvb [(size_t)MROWS * 3 * Cdim];
__device__ __align__(16) bf16  g_attnob[(size_t)MROWS * Cdim];
__device__ __align__(16) float g_h    [(size_t)MROWS * Cdim];
__device__ __align__(16) bf16  g_ln2b [(size_t)MROWS * Cdim];
__device__ __align__(16) bf16  g_hidb [(size_t)MROWS * HID];
__device__ __align__(16) bf16  g_qkvwT[576 * 192];
__device__ __align__(16) bf16  g_projwT[192 * 192];
__device__ __align__(16) bf16  g_w1T  [HID * 192];
__device__ __align__(16) bf16  g_w2T  [192 * HID];

// ------------------------------ helpers ------------------------------------
__device__ __forceinline__ void cpasync16(bf16* dst, const bf16* src) {
    uint32_t d = (uint32_t)__cvta_generic_to_shared(dst);
    asm volatile("cp.async.cg.shared.global [%0], [%1], 16;" :: "r"(d), "l"(src));
}
#define CP_COMMIT() asm volatile("cp.async.commit_group;" ::: "memory")

__device__ __forceinline__ void mma_bf16(float* d, const uint32_t* a, const uint32_t* b) {
    asm volatile(
        "mma.sync.aligned.m16n8k16.row.col.f32.bf16.bf16.f32 "
        "{%0,%1,%2,%3}, {%4,%5,%6,%7}, {%8,%9}, {%0,%1,%2,%3};"
        : "+f"(d[0]), "+f"(d[1]), "+f"(d[2]), "+f"(d[3])
        : "r"(a[0]), "r"(a[1]), "r"(a[2]), "r"(a[3]), "r"(b[0]), "r"(b[1]));
}

__device__ __forceinline__ int permrow(int rw) {
    int win = rw / NTOK, n = rw - win * NTOK;
    int b   = win >> 6, wi = win & 63;
    int wh  = wi >> 3,  ww = wi & 7;
    int i   = n / WSZ,  j  = n - i * WSZ;
    int hs  = wh * WSZ + i + SSH; if (hs >= HW) hs -= HW;
    int ws  = ww * WSZ + j + SSH; if (ws >= HW) ws -= HW;
    return b * (HW * HW) + hs * HW + ws;
}

// ------------------ merged weight transpose (fp32 -> bf16 T) ----------------
__global__ void transpose_all(const float* __restrict__ qkvw,
                              const float* __restrict__ projw,
                              const float* __restrict__ w1,
                              const float* __restrict__ w2,
                              bf16* __restrict__ o0, bf16* __restrict__ o1,
                              bf16* __restrict__ o2, bf16* __restrict__ o3) {
    __shared__ float t[32][33];
    const float* in; bf16* out; int R, C;
    switch (blockIdx.z) {
        case 0: in = qkvw;  out = o0; R = 192; C = 576; break;
        case 1: in = projw; out = o1; R = 192; C = 192; break;
        case 2: in = w1;    out = o2; R = 192; C = 768; break;
        default:in = w2;    out = o3; R = 768; C = 192; break;
    }
    int bx = blockIdx.x * 32, by = blockIdx.y * 32;
    if (bx >= C || by >= R) return;
    int x = threadIdx.x, y0 = threadIdx.y;
    #pragma unroll
    for (int j = 0; j < 32; j += 8)
        t[y0 + j][x] = in[(size_t)(by + y0 + j) * C + bx + x];
    __syncthreads();
    #pragma unroll
    for (int j = 0; j < 32; j += 8)
        out[(size_t)(bx + y0 + j) * R + by + x] = __float2bfloat16_rn(t[x][y0 + j]);
}

// ------------------------- LN1 (warp/row, permuted read) -------------------
__global__ __launch_bounds__(256)
void ln_kernel(const float* __restrict__ in, const float* __restrict__ gamma,
               const float* __restrict__ beta, bf16* __restrict__ out) {
    int wid = threadIdx.x >> 5, lane = threadIdx.x & 31;
    int row = blockIdx.x * 8 + wid;
    int src = permrow(row);
    const float* p = in + (size_t)src * Cdim;

    float v[6];
    #pragma unroll
    for (int j = 0; j < 3; j++) {
        float2 xv = *(const float2*)&p[2 * lane + 64 * j];
        v[2 * j] = xv.x; v[2 * j + 1] = xv.y;
    }
    float s = v[0] + v[1] + v[2] + v[3] + v[4] + v[5];
    #pragma unroll
    for (int o = 16; o; o >>= 1) s += __shfl_xor_sync(0xffffffffu, s, o);
    float mu = s * (1.0f / Cdim);
    float sq = 0.f;
    #pragma unroll
    for (int j = 0; j < 6; j++) { v[j] -= mu; sq += v[j] * v[j]; }
    #pragma unroll
    for (int o = 16; o; o >>= 1) sq += __shfl_xor_sync(0xffffffffu, sq, o);
    float inv = rsqrtf(sq * (1.0f / Cdim) + 1e-5f);

    bf16* q = out + (size_t)row * Cdim;
    #pragma unroll
    for (int j = 0; j < 3; j++) {
        int c = 2 * lane + 64 * j;
        float o0 = v[2 * j] * inv * gamma[c] + beta[c];
        float o1 = v[2 * j + 1] * inv * gamma[c + 1] + beta[c + 1];
        *(bf162*)(q + c) = __floats2bfloat162_rn(o0, o1);
    }
}

// --------------------------- bf16 mma.sync GEMM ----------------------------
// C[M,N] = A[M,K] @ BT[N,K]^T. CTA 128 x (32*NWARP_N_TILES...); 8 warps 2x4,
// warp 64 x (NT*8). k-chunk 32. EPI: 0 plain, 1 GELU, 2 permrow+resid+LN2, 3 +resid
template<int CTA_N>
__device__ __forceinline__ void gload(const bf16* __restrict__ A,
                                      const bf16* __restrict__ BT,
                                      bf16* As, bf16* Bs,
                                      int mBase, int nBase, int K, int k0, int tid) {
    #pragma unroll
    for (int i = 0; i < 2; i++) {
        int idx = tid + i * 256;
        int r = idx >> 2, ch = idx & 3;
        cpasync16(As + r * SROW + ch * 8, A + (size_t)(mBase + r) * K + k0 + ch * 8);
    }
    #pragma unroll
    for (int i = 0; i < CTA_N * 4; i += 256) {
        int idx = tid + i;
        if (CTA_N * 4 % 256 == 0 || idx < CTA_N * 4) {
            int r = idx >> 2, ch = idx & 3;
            cpasync16(Bs + r * SROW + ch * 8, BT + (size_t)(nBase + r) * K + k0 + ch * 8);
        }
    }
    CP_COMMIT();
}

template<int EPI, int NT, bool OBF16>
__global__ __launch_bounds__(256)
void tc_gemm(const bf16* __restrict__ A, const bf16* __restrict__ BT,
             const float* __restrict__ bias, void* __restrict__ Cv,
             int N, int K, const float* __restrict__ resid,
             bf16* __restrict__ C2, const float* __restrict__ g2,
             const float* __restrict__ b2v) {
    constexpr int CTA_N = NT * 32;
    extern __shared__ __align__(16) bf16 sm[];
    bf16* AsBase = sm;
    bf16* BsBase = sm + 2 * 128 * SROW;

    int tid  = threadIdx.x;
    int wid  = tid >> 5, lane = tid & 31;
    int g    = lane >> 2, tig = lane & 3;
    int wm   = wid & 1, wn = wid >> 1;         // 2 x 4 warp grid
    int mBase = blockIdx.x * 128;
    int nBase = blockIdx.y * CTA_N;
    int nk = K >> 5;

    float acc[4][NT][4];
    #pragma unroll
    for (int mt = 0; mt < 4; mt++)
        #pragma unroll
        for (int nt = 0; nt < NT; nt++)
            #pragma unroll
            for (int e = 0; e < 4; e++) acc[mt][nt][e] = 0.f;

    gload<CTA_N>(A, BT, AsBase, BsBase, mBase, nBase, K, 0, tid);

    for (int kt = 0; kt < nk; kt++) {
        int buf = kt & 1;
        if (kt + 1 < nk) {
            gload<CTA_N>(A, BT, AsBase + (buf ^ 1) * 128 * SROW,
                         BsBase + (buf ^ 1) * CTA_N * SROW,
                         mBase, nBase, K, (kt + 1) << 5, tid);
            asm volatile("cp.async.wait_group 1;" ::: "memory");
        } else {
            asm volatile("cp.async.wait_group 0;" ::: "memory");
        }
        __syncthreads();

        const bf16* As = AsBase + buf * 128 * SROW;
        const bf16* Bs = BsBase + buf * CTA_N * SROW;

        #pragma unroll
        for (int s = 0; s < 2; s++) {
            uint32_t a[4][4], b[NT][2];
            #pragma unroll
            for (int mt = 0; mt < 4; mt++) {
                int r = wm * 64 + mt * 16 + g;
                const bf16* p0 = As + r * SROW + s * 16 + 2 * tig;
                const bf16* p1 = p0 + 8 * SROW;
                a[mt][0] = *(const uint32_t*)p0;
                a[mt][1] = *(const uint32_t*)p1;
                a[mt][2] = *(const uint32_t*)(p0 + 8);
                a[mt][3] = *(const uint32_t*)(p1 + 8);
            }
            #pragma unroll
            for (int nt = 0; nt < NT; nt++) {
                int n = wn * NT * 8 + nt * 8 + g;
                const bf16* p = Bs + n * SROW + s * 16 + 2 * tig;
                b[nt][0] = *(const uint32_t*)p;
                b[nt][1] = *(const uint32_t*)(p + 8);
            }
            #pragma unroll
            for (int mt = 0; mt < 4; mt++)
                #pragma unroll
                for (int nt = 0; nt < NT; nt++)
                    mma_bf16(acc[mt][nt], a[mt], b[nt]);
        }
        __syncthreads();
    }

    // ---------------- epilogue ----------------
    float* s_sum = (float*)(sm + 2 * (128 + CTA_N) * SROW);
    float* s_sq  = s_sum + 512;

    #pragma unroll
    for (int mt = 0; mt < 4; mt++) {
        int lr0 = wm * 64 + mt * 16 + g;
        int lr1 = lr0 + 8;
        int r0 = mBase + lr0, r1 = mBase + lr1;
        int p0 = r0, p1 = r1;
        if (EPI == 2) { p0 = permrow(r0); p1 = permrow(r1); }

        float s0 = 0.f, q0 = 0.f, s1 = 0.f, q1 = 0.f;
        #pragma unroll
        for (int nt = 0; nt < NT; nt++) {
            int c = nBase + wn * NT * 8 + nt * 8 + 2 * tig;
            float2 bv = *(const float2*)(bias + c);
            float v0 = acc[mt][nt][0] + bv.x;
            float v1 = acc[mt][nt][1] + bv.y;
            float v2 = acc[mt][nt][2] + bv.x;
            float v3 = acc[mt][nt][3] + bv.y;
            if (EPI == 1) {
                v0 = 0.5f * v0 * (1.0f + erff(v0 * 0.70710678118654752f));
                v1 = 0.5f * v1 * (1.0f + erff(v1 * 0.70710678118654752f));
                v2 = 0.5f * v2 * (1.0f + erff(v2 * 0.70710678118654752f));
                v3 = 0.5f * v3 * (1.0f + erff(v3 * 0.70710678118654752f));
            } else if (EPI == 2) {
                float2 ra = *(const float2*)(resid + (size_t)p0 * Cdim + c);
                float2 rb = *(const float2*)(resid + (size_t)p1 * Cdim + c);
                v0 += ra.x; v1 += ra.y; v2 += rb.x; v3 += rb.y;
                s0 += v0 + v1; q0 += v0 * v0 + v1 * v1;
                s1 += v2 + v3; q1 += v2 * v2 + v3 * v3;
                acc[mt][nt][0] = v0; acc[mt][nt][1] = v1;
                acc[mt][nt][2] = v2; acc[mt][nt][3] = v3;
            } else if (EPI == 3) {
                float2 ra = *(const float2*)(resid + (size_t)r0 * Cdim + c);
                float2 rb = *(const float2*)(resid + (size_t)r1 * Cdim + c);
                v0 += ra.x; v1 += ra.y; v2 += rb.x; v3 += rb.y;
            }
            if (OBF16) {
                bf16* Cb = (bf16*)Cv;
                *(bf162*)(Cb + (size_t)p0 * N + c) = __floats2bfloat162_rn(v0, v1);
                *(bf162*)(Cb + (size_t)p1 * N + c) = __floats2bfloat162_rn(v2, v3);
            } else {
                float* Cf = (float*)Cv;
                *(float2*)(Cf + (size_t)p0 * N + c) = make_float2(v0, v1);
                *(float2*)(Cf + (size_t)p1 * N + c) = make_float2(v2, v3);
            }
        }
        if (EPI == 2) {
            #pragma unroll
            for (int o = 1; o < 4; o <<= 1) {
                s0 += __shfl_xor_sync(0xffffffffu, s0, o);
                q0 += __shfl_xor_sync(0xffffffffu, q0, o);
                s1 += __shfl_xor_sync(0xffffffffu, s1, o);
                q1 += __shfl_xor_sync(0xffffffffu, q1, o);
            }
            if (tig == 0) {
                s_sum[wn * 128 + lr0] = s0;  s_sq[wn * 128 + lr0] = q0;
                s_sum[wn * 128 + lr1] = s1;  s_sq[wn * 128 + lr1] = q1;
            }
        }
    }

    if (EPI == 2) {
        __syncthreads();
        #pragma unroll
        for (int mt = 0; mt < 4; mt++) {
            int lr0 = wm * 64 + mt * 16 + g;
            int lr1 = lr0 + 8;
            int p0 = permrow(mBase + lr0), p1 = permrow(mBase + lr1);
            float su0 = s_sum[lr0] + s_sum[128 + lr0] + s_sum[256 + lr0] + s_sum[384 + lr0];
            float sq0 = s_sq[lr0]  + s_sq[128 + lr0]  + s_sq[256 + lr0]  + s_sq[384 + lr0];
            float su1 = s_sum[lr1] + s_sum[128 + lr1] + s_sum[256 + lr1] + s_sum[384 + lr1];
            float sq1 = s_sq[lr1]  + s_sq[128 + lr1]  + s_sq[256 + lr1]  + s_sq[384 + lr1];
            float mu0 = su0 * (1.0f / Cdim);
            float mu1 = su1 * (1.0f / Cdim);
            float iv0 = rsqrtf(sq0 * (1.0f / Cdim) - mu0 * mu0 + 1e-5f);
            float iv1 = rsqrtf(sq1 * (1.0f / Cdim) - mu1 * mu1 + 1e-5f);
            #pragma unroll
            for (int nt = 0; nt < NT; nt++) {
                int c = wn * NT * 8 + nt * 8 + 2 * tig;
                float2 gv = *(const float2*)(g2 + c);
                float2 bb = *(const float2*)(b2v + c);
                float o0 = (acc[mt][nt][0] - mu0) * iv0 * gv.x + bb.x;
                float o1 = (acc[mt][nt][1] - mu0) * iv0 * gv.y + bb.y;
                float o2 = (acc[mt][nt][2] - mu1) * iv1 * gv.x + bb.x;
                float o3 = (acc[mt][nt][3] - mu1) * iv1 * gv.y + bb.y;
                *(bf162*)(C2 + (size_t)p0 * Cdim + c) = __floats2bfloat162_rn(o0, o1);
                *(bf162*)(C2 + (size_t)p1 * Cdim + c) = __floats2bfloat162_rn(o2, o3);
            }
        }
    }
}

// ----------------------------- Attention -----------------------------------
__global__ __launch_bounds__(256)
void attn_kernel(const float* __restrict__ rpb_table) {
    __shared__ float qs[NTOK][HDIM];
    __shared__ float ks[NTOK][HDIM];
    __shared__ float vs[NTOK][HDIM];
    __shared__ float S[NTOK][NTOK];

    int win  = blockIdx.x / NHEADS;
    int head = blockIdx.x - win * NHEADS;
    int tid  = threadIdx.x;
    int wi = win & 63;
    int wh = wi >> 3, ww = wi & 7;

    const bf16* base = g_qkvb + (size_t)win * NTOK * (3 * Cdim) + head * HDIM;

    for (int idx = tid; idx < NTOK * 16; idx += 256) {
        int n = idx >> 4, p = idx & 15;
        const bf162* r2 = (const bf162*)(base + (size_t)n * (3 * Cdim));
        float2 q = __bfloat1622float2(r2[p]);
        q.x *= SCALE; q.y *= SCALE;
        float2 k = __bfloat1622float2(r2[96 + p]);
        float2 v = __bfloat1622float2(r2[192 + p]);
        qs[n][2 * p] = q.x; qs[n][2 * p + 1] = q.y;
        ks[n][2 * p] = k.x; ks[n][2 * p + 1] = k.y;
        vs[n][2 * p] = v.x; vs[n][2 * p + 1] = v.y;
    }
    __syncthreads();

    for (int e = tid; e < NTOK * NTOK; e += 256) {
        int i = e / NTOK, j = e - i * NTOK;
        const float4* qp = (const float4*)qs[i];
        const float4* kp = (const float4*)ks[j];
        float dot = 0.f;
        #pragma unroll
        for (int d = 0; d < 8; d++) {
            float4 qv = qp[d], kv = kp[d];
            dot += qv.x * kv.x + qv.y * kv.y + qv.z * kv.z + qv.w * kv.w;
        }
        int ri = i / WSZ, ci = i - ri * WSZ;
        int rj = j / WSZ, cj = j - rj * WSZ;
        dot += rpb_table[((ri - rj + 6) * 13 + (ci - cj + 6)) * NHEADS + head];
        int hi = wh * WSZ + ri, wiC = ww * WSZ + ci;
        int hj = wh * WSZ + rj, wjC = ww * WSZ + cj;
        int gi = (hi < 49 ? 0 : (hi < 53 ? 1 : 2)) * 3 + (wiC < 49 ? 0 : (wiC < 53 ? 1 : 2));
        int gj = (hj < 49 ? 0 : (hj < 53 ? 1 : 2)) * 3 + (wjC < 49 ? 0 : (wjC < 53 ? 1 : 2));
        if (gi != gj) dot -= 100.0f;
        S[i][j] = dot;
    }
    __syncthreads();

    int warp = tid >> 5, lane = tid & 31;
    for (int r = warp; r < NTOK; r += 8) {
        float v0 = (lane < NTOK) ? S[r][lane] : -1e30f;
        float v1 = (lane + 32 < NTOK) ? S[r][lane + 32] : -1e30f;
        float m = fmaxf(v0, v1);
        #pragma unroll
        for (int o = 16; o; o >>= 1) m = fmaxf(m, __shfl_xor_sync(0xffffffffu, m, o));
        float e0 = (lane < NTOK) ? __expf(v0 - m) : 0.f;
        float e1 = (lane + 32 < NTOK) ? __expf(v1 - m) : 0.f;
        float s = e0 + e1;
        #pragma unroll
        for (int o = 16; o; o >>= 1) s += __shfl_xor_sync(0xffffffffu, s, o);
        float inv = __fdividef(1.0f, s);
        if (lane < NTOK)      S[r][lane]      = e0 * inv;
        if (lane + 32 < NTOK) S[r][lane + 32] = e1 * inv;
    }
    __syncthreads();

    for (int e = tid; e < NTOK * 8; e += 256) {
        int n = e >> 3, dg = e & 7;
        float4 acc = make_float4(0.f, 0.f, 0.f, 0.f);
        #pragma unroll 7
        for (int m = 0; m < NTOK; m++) {
            float s = S[n][m];
            float4 v = ((const float4*)vs[m])[dg];
            acc.x += s * v.x; acc.y += s * v.y; acc.z += s * v.z; acc.w += s * v.w;
        }
        bf16* o = g_attnob + (size_t)(win * NTOK + n) * Cdim + head * HDIM + dg * 4;
        *(bf162*)o       = __floats2bfloat162_rn(acc.x, acc.y);
        *(bf162*)(o + 2) = __floats2bfloat162_rn(acc.z, acc.w);
    }
}

// ------------------------------ launcher -----------------------------------
#define SM3 (2 * (128 + 96) * SROW * 2)                    // 35840 B
#define SM6 (2 * (128 + 192) * SROW * 2 + 1024 * 4)        // 55296 B

extern "C" void kernel_launch(void* const* d_in, const int* in_sizes, int n_in,
                              void* d_out, int out_size) {
    const float* x      = (const float*)d_in[0];
    const float* qkv_w  = (const float*)d_in[1];
    const float* qkv_b  = (const float*)d_in[2];
    const float* proj_w = (const float*)d_in[3];
    const float* proj_b = (const float*)d_in[4];
    const float* rpb    = (const float*)d_in[5];
    const float* ln1_g  = (const float*)d_in[6];
    const float* ln1_b  = (const float*)d_in[7];
    const float* ln2_g  = (const float*)d_in[8];
    const float* ln2_b  = (const float*)d_in[9];
    const float* w1     = (const float*)d_in[10];
    const float* b1     = (const float*)d_in[11];
    const float* w2     = (const float*)d_in[12];
    const float* b2     = (const float*)d_in[13];
    float* out = (float*)d_out;

    bf16 *p_win, *p_qkv, *p_attno, *p_ln2, *p_hid;
    bf16 *p_qkvwT, *p_projwT, *p_w1T, *p_w2T;
    float *p_h;
    cudaGetSymbolAddress((void**)&p_win,    g_winb);
    cudaGetSymbolAddress((void**)&p_qkv,    g_qkvb);
    cudaGetSymbolAddress((void**)&p_attno,  g_attnob);
    cudaGetSymbolAddress((void**)&p_h,      g_h);
    cudaGetSymbolAddress((void**)&p_ln2,    g_ln2b);
    cudaGetSymbolAddress((void**)&p_hid,    g_hidb);
    cudaGetSymbolAddress((void**)&p_qkvwT,  g_qkvwT);
    cudaGetSymbolAddress((void**)&p_projwT, g_projwT);
    cudaGetSymbolAddress((void**)&p_w1T,    g_w1T);
    cudaGetSymbolAddress((void**)&p_w2T,    g_w2T);

    cudaFuncSetAttribute(tc_gemm<0,3,true>,  cudaFuncAttributeMaxDynamicSharedMemorySize, SM3);
    cudaFuncSetAttribute(tc_gemm<1,3,true>,  cudaFuncAttributeMaxDynamicSharedMemorySize, SM3);
    cudaFuncSetAttribute(tc_gemm<2,6,false>, cudaFuncAttributeMaxDynamicSharedMemorySize, SM6);
    cudaFuncSetAttribute(tc_gemm<3,3,false>, cudaFuncAttributeMaxDynamicSharedMemorySize, SM3);

    // 0. all weight transposes (fp32 -> bf16, K-major)
    transpose_all<<<dim3(24, 24, 4), dim3(32, 8)>>>(qkv_w, proj_w, w1, w2,
                                                    p_qkvwT, p_projwT, p_w1T, p_w2T);

    // 1. LN1 + shifted-window partition -> bf16
    ln_kernel<<<MROWS / 8, 256>>>(x, ln1_g, ln1_b, p_win);

    // 2. QKV: (100352,192) @ (192,576) -> bf16
    tc_gemm<0,3,true><<<dim3(MROWS / 128, 6), 256, SM3>>>(
        p_win, p_qkvwT, qkv_b, p_qkv, 576, 192, nullptr, nullptr, nullptr, nullptr);

    // 3. windowed attention -> bf16
    attn_kernel<<<NWIN * NHEADS, 256>>>(rpb);

    // 4. proj + window-reverse + residual(x) + fused LN2 (g_h fp32, g_ln2 bf16)
    tc_gemm<2,6,false><<<dim3(MROWS / 128, 1), 256, SM6>>>(
        p_attno, p_projwT, proj_b, p_h, 192, 192, x, p_ln2, ln2_g, ln2_b);

    // 5. MLP1 + GELU -> bf16
    tc_gemm<1,3,true><<<dim3(MROWS / 128, 8), 256, SM3>>>(
        p_ln2, p_w1T, b1, p_hid, HID, 192, nullptr, nullptr, nullptr, nullptr);

    // 6. MLP2 + residual(h) -> fp32 out
    tc_gemm<3,3,false><<<dim3(MROWS / 128, 2), 256, SM3>>>(
        p_hid, p_w2T, b2, out, 192, HID, p_h, nullptr, nullptr, nullptr);
}

// round 7
// speedup vs baseline: 2.9539x; 2.3805x over previous
#include <cuda_runtime.h>
#include <cuda_bf16.h>
#include <cstdint>

// ---------------------------------------------------------------------------
// SwinBlock: B=32, H=W=56, C=192, heads=6, head_dim=32, WS=7, SS=3, N=49
// bf16 mma.sync everywhere: GEMMs (k64 chunks) + tensor-core attention.
// ---------------------------------------------------------------------------

#define HW      56
#define Cdim    192
#define NHEADS  6
#define HDIM    32
#define WSZ     7
#define SSH     3
#define NTOK    49
#define NWIN    2048
#define MROWS   100352
#define HID     768
#define SCALE   0.17677669529663687f
#define SROW    72      // bf16 elems per smem row (64 data + 8 pad)

typedef __nv_bfloat16 bf16;
typedef __nv_bfloat162 bf162;

// -------------------------- scratch (device globals) -----------------------
__device__ __align__(16) bf16  g_winb [(size_t)MROWS * Cdim];
__device__ __align__(16) bf16  g_qkvb [(size_t)MROWS * 3 * Cdim];
__device__ __align__(16) bf16  g_attnob[(size_t)MROWS * Cdim];
__device__ __align__(16) float g_h    [(size_t)MROWS * Cdim];
__device__ __align__(16) bf16  g_ln2b [(size_t)MROWS * Cdim];
__device__ __align__(16) bf16  g_hidb [(size_t)MROWS * HID];
__device__ __align__(16) bf16  g_qkvwT[576 * 192];
__device__ __align__(16) bf16  g_projwT[192 * 192];
__device__ __align__(16) bf16  g_w1T  [HID * 192];
__device__ __align__(16) bf16  g_w2T  [192 * HID];

// ------------------------------ helpers ------------------------------------
__device__ __forceinline__ void cpasync16(bf16* dst, const bf16* src) {
    uint32_t d = (uint32_t)__cvta_generic_to_shared(dst);
    asm volatile("cp.async.cg.shared.global [%0], [%1], 16;" :: "r"(d), "l"(src));
}
#define CP_COMMIT() asm volatile("cp.async.commit_group;" ::: "memory")

__device__ __forceinline__ void mma_bf16(float* d, const uint32_t* a, const uint32_t* b) {
    asm volatile(
        "mma.sync.aligned.m16n8k16.row.col.f32.bf16.bf16.f32 "
        "{%0,%1,%2,%3}, {%4,%5,%6,%7}, {%8,%9}, {%0,%1,%2,%3};"
        : "+f"(d[0]), "+f"(d[1]), "+f"(d[2]), "+f"(d[3])
        : "r"(a[0]), "r"(a[1]), "r"(a[2]), "r"(a[3]), "r"(b[0]), "r"(b[1]));
}

__device__ __forceinline__ int permrow(int rw) {
    int win = rw / NTOK, n = rw - win * NTOK;
    int b   = win >> 6, wi = win & 63;
    int wh  = wi >> 3,  ww = wi & 7;
    int i   = n / WSZ,  j  = n - i * WSZ;
    int hs  = wh * WSZ + i + SSH; if (hs >= HW) hs -= HW;
    int ws  = ww * WSZ + j + SSH; if (ws >= HW) ws -= HW;
    return b * (HW * HW) + hs * HW + ws;
}

// ------------------ merged weight transpose (fp32 -> bf16 T) ----------------
__global__ void transpose_all(const float* __restrict__ qkvw,
                              const float* __restrict__ projw,
                              const float* __restrict__ w1,
                              const float* __restrict__ w2,
                              bf16* __restrict__ o0, bf16* __restrict__ o1,
                              bf16* __restrict__ o2, bf16* __restrict__ o3) {
    __shared__ float t[32][33];
    const float* in; bf16* out; int R, C;
    switch (blockIdx.z) {
        case 0: in = qkvw;  out = o0; R = 192; C = 576; break;
        case 1: in = projw; out = o1; R = 192; C = 192; break;
        case 2: in = w1;    out = o2; R = 192; C = 768; break;
        default:in = w2;    out = o3; R = 768; C = 192; break;
    }
    int bx = blockIdx.x * 32, by = blockIdx.y * 32;
    if (bx >= C || by >= R) return;
    int x = threadIdx.x, y0 = threadIdx.y;
    #pragma unroll
    for (int j = 0; j < 32; j += 8)
        t[y0 + j][x] = in[(size_t)(by + y0 + j) * C + bx + x];
    __syncthreads();
    #pragma unroll
    for (int j = 0; j < 32; j += 8)
        out[(size_t)(bx + y0 + j) * R + by + x] = __float2bfloat16_rn(t[x][y0 + j]);
}

// ------------------------- LN1 (warp/row, permuted read) -------------------
__global__ __launch_bounds__(256)
void ln_kernel(const float* __restrict__ in, const float* __restrict__ gamma,
               const float* __restrict__ beta, bf16* __restrict__ out) {
    int wid = threadIdx.x >> 5, lane = threadIdx.x & 31;
    int row = blockIdx.x * 8 + wid;
    int src = permrow(row);
    const float* p = in + (size_t)src * Cdim;

    float v[6];
    #pragma unroll
    for (int j = 0; j < 3; j++) {
        float2 xv = *(const float2*)&p[2 * lane + 64 * j];
        v[2 * j] = xv.x; v[2 * j + 1] = xv.y;
    }
    float s = v[0] + v[1] + v[2] + v[3] + v[4] + v[5];
    #pragma unroll
    for (int o = 16; o; o >>= 1) s += __shfl_xor_sync(0xffffffffu, s, o);
    float mu = s * (1.0f / Cdim);
    float sq = 0.f;
    #pragma unroll
    for (int j = 0; j < 6; j++) { v[j] -= mu; sq += v[j] * v[j]; }
    #pragma unroll
    for (int o = 16; o; o >>= 1) sq += __shfl_xor_sync(0xffffffffu, sq, o);
    float inv = rsqrtf(sq * (1.0f / Cdim) + 1e-5f);

    bf16* q = out + (size_t)row * Cdim;
    #pragma unroll
    for (int j = 0; j < 3; j++) {
        int c = 2 * lane + 64 * j;
        float o0 = v[2 * j] * inv * gamma[c] + beta[c];
        float o1 = v[2 * j + 1] * inv * gamma[c + 1] + beta[c + 1];
        *(bf162*)(q + c) = __floats2bfloat162_rn(o0, o1);
    }
}

// --------------------------- bf16 mma.sync GEMM ----------------------------
// C[M,N] = A[M,K] @ BT[N,K]^T. CTA 128 x (NT*32); 8 warps 2x4, warp 64 x NT*8.
// k-chunk 64. EPI: 0 plain, 1 GELU, 2 permrow+resid+LN2, 3 +resid
template<int CTA_N>
__device__ __forceinline__ void gload(const bf16* __restrict__ A,
                                      const bf16* __restrict__ BT,
                                      bf16* As, bf16* Bs,
                                      int mBase, int nBase, int K, int k0, int tid) {
    #pragma unroll
    for (int i = 0; i < 4; i++) {
        int idx = tid + i * 256;
        int r = idx >> 3, ch = idx & 7;
        cpasync16(As + r * SROW + ch * 8, A + (size_t)(mBase + r) * K + k0 + ch * 8);
    }
    #pragma unroll
    for (int i = 0; i < CTA_N * 8; i += 256) {
        int idx = tid + i;
        int r = idx >> 3, ch = idx & 7;
        cpasync16(Bs + r * SROW + ch * 8, BT + (size_t)(nBase + r) * K + k0 + ch * 8);
    }
    CP_COMMIT();
}

template<int EPI, int NT, bool OBF16>
__global__ __launch_bounds__(256)
void tc_gemm(const bf16* __restrict__ A, const bf16* __restrict__ BT,
             const float* __restrict__ bias, void* __restrict__ Cv,
             int N, int K, const float* __restrict__ resid,
             bf16* __restrict__ C2, const float* __restrict__ g2,
             const float* __restrict__ b2v) {
    constexpr int CTA_N = NT * 32;
    extern __shared__ __align__(16) bf16 sm[];
    bf16* AsBase = sm;
    bf16* BsBase = sm + 2 * 128 * SROW;

    int tid  = threadIdx.x;
    int wid  = tid >> 5, lane = tid & 31;
    int g    = lane >> 2, tig = lane & 3;
    int wm   = wid & 1, wn = wid >> 1;         // 2 x 4 warp grid
    int mBase = blockIdx.x * 128;
    int nBase = blockIdx.y * CTA_N;
    int nk = K >> 6;

    float acc[4][NT][4];
    #pragma unroll
    for (int mt = 0; mt < 4; mt++)
        #pragma unroll
        for (int nt = 0; nt < NT; nt++)
            #pragma unroll
            for (int e = 0; e < 4; e++) acc[mt][nt][e] = 0.f;

    gload<CTA_N>(A, BT, AsBase, BsBase, mBase, nBase, K, 0, tid);

    for (int kt = 0; kt < nk; kt++) {
        int buf = kt & 1;
        if (kt + 1 < nk) {
            gload<CTA_N>(A, BT, AsBase + (buf ^ 1) * 128 * SROW,
                         BsBase + (buf ^ 1) * CTA_N * SROW,
                         mBase, nBase, K, (kt + 1) << 6, tid);
            asm volatile("cp.async.wait_group 1;" ::: "memory");
        } else {
            asm volatile("cp.async.wait_group 0;" ::: "memory");
        }
        __syncthreads();

        const bf16* As = AsBase + buf * 128 * SROW;
        const bf16* Bs = BsBase + buf * CTA_N * SROW;

        #pragma unroll
        for (int s = 0; s < 4; s++) {
            uint32_t a[4][4], b[NT][2];
            #pragma unroll
            for (int mt = 0; mt < 4; mt++) {
                int r = wm * 64 + mt * 16 + g;
                const bf16* p0 = As + r * SROW + s * 16 + 2 * tig;
                const bf16* p1 = p0 + 8 * SROW;
                a[mt][0] = *(const uint32_t*)p0;
                a[mt][1] = *(const uint32_t*)p1;
                a[mt][2] = *(const uint32_t*)(p0 + 8);
                a[mt][3] = *(const uint32_t*)(p1 + 8);
            }
            #pragma unroll
            for (int nt = 0; nt < NT; nt++) {
                int n = wn * NT * 8 + nt * 8 + g;
                const bf16* p = Bs + n * SROW + s * 16 + 2 * tig;
                b[nt][0] = *(const uint32_t*)p;
                b[nt][1] = *(const uint32_t*)(p + 8);
            }
            #pragma unroll
            for (int mt = 0; mt < 4; mt++)
                #pragma unroll
                for (int nt = 0; nt < NT; nt++)
                    mma_bf16(acc[mt][nt], a[mt], b[nt]);
        }
        __syncthreads();
    }

    // ---------------- epilogue ----------------
    float* s_sum = (float*)(sm + 2 * (128 + CTA_N) * SROW);
    float* s_sq  = s_sum + 512;

    #pragma unroll
    for (int mt = 0; mt < 4; mt++) {
        int lr0 = wm * 64 + mt * 16 + g;
        int lr1 = lr0 + 8;
        int r0 = mBase + lr0, r1 = mBase + lr1;
        int p0 = r0, p1 = r1;
        if (EPI == 2) { p0 = permrow(r0); p1 = permrow(r1); }

        float s0 = 0.f, q0 = 0.f, s1 = 0.f, q1 = 0.f;
        #pragma unroll
        for (int nt = 0; nt < NT; nt++) {
            int c = nBase + wn * NT * 8 + nt * 8 + 2 * tig;
            float2 bv = *(const float2*)(bias + c);
            float v0 = acc[mt][nt][0] + bv.x;
            float v1 = acc[mt][nt][1] + bv.y;
            float v2 = acc[mt][nt][2] + bv.x;
            float v3 = acc[mt][nt][3] + bv.y;
            if (EPI == 1) {
                v0 = 0.5f * v0 * (1.0f + erff(v0 * 0.70710678118654752f));
                v1 = 0.5f * v1 * (1.0f + erff(v1 * 0.70710678118654752f));
                v2 = 0.5f * v2 * (1.0f + erff(v2 * 0.70710678118654752f));
                v3 = 0.5f * v3 * (1.0f + erff(v3 * 0.70710678118654752f));
            } else if (EPI == 2) {
                float2 ra = *(const float2*)(resid + (size_t)p0 * Cdim + c);
                float2 rb = *(const float2*)(resid + (size_t)p1 * Cdim + c);
                v0 += ra.x; v1 += ra.y; v2 += rb.x; v3 += rb.y;
                s0 += v0 + v1; q0 += v0 * v0 + v1 * v1;
                s1 += v2 + v3; q1 += v2 * v2 + v3 * v3;
                acc[mt][nt][0] = v0; acc[mt][nt][1] = v1;
                acc[mt][nt][2] = v2; acc[mt][nt][3] = v3;
            } else if (EPI == 3) {
                float2 ra = *(const float2*)(resid + (size_t)r0 * Cdim + c);
                float2 rb = *(const float2*)(resid + (size_t)r1 * Cdim + c);
                v0 += ra.x; v1 += ra.y; v2 += rb.x; v3 += rb.y;
            }
            if (OBF16) {
                bf16* Cb = (bf16*)Cv;
                *(bf162*)(Cb + (size_t)p0 * N + c) = __floats2bfloat162_rn(v0, v1);
                *(bf162*)(Cb + (size_t)p1 * N + c) = __floats2bfloat162_rn(v2, v3);
            } else {
                float* Cf = (float*)Cv;
                *(float2*)(Cf + (size_t)p0 * N + c) = make_float2(v0, v1);
                *(float2*)(Cf + (size_t)p1 * N + c) = make_float2(v2, v3);
            }
        }
        if (EPI == 2) {
            #pragma unroll
            for (int o = 1; o < 4; o <<= 1) {
                s0 += __shfl_xor_sync(0xffffffffu, s0, o);
                q0 += __shfl_xor_sync(0xffffffffu, q0, o);
                s1 += __shfl_xor_sync(0xffffffffu, s1, o);
                q1 += __shfl_xor_sync(0xffffffffu, q1, o);
            }
            if (tig == 0) {
                s_sum[wn * 128 + lr0] = s0;  s_sq[wn * 128 + lr0] = q0;
                s_sum[wn * 128 + lr1] = s1;  s_sq[wn * 128 + lr1] = q1;
            }
        }
    }

    if (EPI == 2) {
        __syncthreads();
        #pragma unroll
        for (int mt = 0; mt < 4; mt++) {
            int lr0 = wm * 64 + mt * 16 + g;
            int lr1 = lr0 + 8;
            int p0 = permrow(mBase + lr0), p1 = permrow(mBase + lr1);
            float su0 = s_sum[lr0] + s_sum[128 + lr0] + s_sum[256 + lr0] + s_sum[384 + lr0];
            float sq0 = s_sq[lr0]  + s_sq[128 + lr0]  + s_sq[256 + lr0]  + s_sq[384 + lr0];
            float su1 = s_sum[lr1] + s_sum[128 + lr1] + s_sum[256 + lr1] + s_sum[384 + lr1];
            float sq1 = s_sq[lr1]  + s_sq[128 + lr1]  + s_sq[256 + lr1]  + s_sq[384 + lr1];
            float mu0 = su0 * (1.0f / Cdim);
            float mu1 = su1 * (1.0f / Cdim);
            float iv0 = rsqrtf(sq0 * (1.0f / Cdim) - mu0 * mu0 + 1e-5f);
            float iv1 = rsqrtf(sq1 * (1.0f / Cdim) - mu1 * mu1 + 1e-5f);
            #pragma unroll
            for (int nt = 0; nt < NT; nt++) {
                int c = wn * NT * 8 + nt * 8 + 2 * tig;
                float2 gv = *(const float2*)(g2 + c);
                float2 bb = *(const float2*)(b2v + c);
                float o0 = (acc[mt][nt][0] - mu0) * iv0 * gv.x + bb.x;
                float o1 = (acc[mt][nt][1] - mu0) * iv0 * gv.y + bb.y;
                float o2 = (acc[mt][nt][2] - mu1) * iv1 * gv.x + bb.x;
                float o3 = (acc[mt][nt][3] - mu1) * iv1 * gv.y + bb.y;
                *(bf162*)(C2 + (size_t)p0 * Cdim + c) = __floats2bfloat162_rn(o0, o1);
                *(bf162*)(C2 + (size_t)p1 * Cdim + c) = __floats2bfloat162_rn(o2, o3);
            }
        }
    }
}

// ---------------------- tensor-core attention ------------------------------
// one block per window; loop over 6 heads; S and PV via bf16 mma.
__global__ __launch_bounds__(256)
void attn_kernel(const float* __restrict__ rpb_table) {
    __shared__ __align__(16) bf16 Qs[64][40];
    __shared__ __align__(16) bf16 Ks[64][40];
    __shared__ __align__(16) bf16 Vt[32][72];    // V transposed: [d][tok]
    __shared__ __align__(16) bf16 Ps[64][72];
    __shared__ float Ssm[64][65];
    __shared__ float rpbs[169];
    __shared__ int   gidm[49];

    int win = blockIdx.x;
    int tid = threadIdx.x;
    int wid = tid >> 5, lane = tid & 31;
    int g = lane >> 2, tig = lane & 3;
    int wi = win & 63;
    int wh = wi >> 3, ww = wi & 7;

    if (tid < 49) {
        int ri = tid / 7, ci = tid - ri * 7;
        int hi = wh * 7 + ri, wc = ww * 7 + ci;
        gidm[tid] = (hi < 49 ? 0 : (hi < 53 ? 1 : 2)) * 3 + (wc < 49 ? 0 : (wc < 53 ? 1 : 2));
    }

    const bf16* base = g_qkvb + (size_t)win * NTOK * 576;

    for (int h = 0; h < NHEADS; h++) {
        __syncthreads();
        // rpb row for this head
        if (tid < 169) rpbs[tid] = rpb_table[tid * NHEADS + h];
        // Q, K tiles (16B chunks)
        for (int idx = tid; idx < 392; idx += 256) {
            int n = idx >> 3, pc = idx & 7;
            int mat = pc >> 2, ch = pc & 3;
            uint4 v = *(const uint4*)(base + (size_t)n * 576 + mat * 192 + h * 32 + ch * 8);
            *(uint4*)((mat ? &Ks[n][0] : &Qs[n][0]) + ch * 8) = v;
        }
        // V transposed
        for (int idx = tid; idx < 196; idx += 256) {
            int n = idx >> 2, ch = idx & 3;
            uint4 v = *(const uint4*)(base + (size_t)n * 576 + 384 + h * 32 + ch * 8);
            bf16 tmp[8]; *(uint4*)tmp = v;
            #pragma unroll
            for (int e = 0; e < 8; e++) Vt[ch * 8 + e][n] = tmp[e];
        }
        for (int idx = tid; idx < 480; idx += 256) {
            int d = idx / 15, n = 49 + idx % 15;
            Vt[d][n] = __float2bfloat16(0.f);
        }
        __syncthreads();

        // ---- S = Q K^T : warps 4m x 2n, warp tile m16 n32 ----
        {
            int wm2 = wid & 3, wn2 = wid >> 2;
            float sf[4][4];
            #pragma unroll
            for (int nt = 0; nt < 4; nt++)
                #pragma unroll
                for (int e = 0; e < 4; e++) sf[nt][e] = 0.f;
            #pragma unroll
            for (int s = 0; s < 2; s++) {
                uint32_t a[4], b[4][2];
                const bf16* p0 = &Qs[wm2 * 16 + g][s * 16 + 2 * tig];
                a[0] = *(const uint32_t*)p0;
                a[1] = *(const uint32_t*)(p0 + 8 * 40);
                a[2] = *(const uint32_t*)(p0 + 8);
                a[3] = *(const uint32_t*)(p0 + 8 * 40 + 8);
                #pragma unroll
                for (int nt = 0; nt < 4; nt++) {
                    const bf16* p = &Ks[wn2 * 32 + nt * 8 + g][s * 16 + 2 * tig];
                    b[nt][0] = *(const uint32_t*)p;
                    b[nt][1] = *(const uint32_t*)(p + 8);
                }
                #pragma unroll
                for (int nt = 0; nt < 4; nt++) mma_bf16(sf[nt], a, b[nt]);
            }
            // store with scale + rpb + mask
            int i0 = wm2 * 16 + g, i1 = i0 + 8;
            #pragma unroll
            for (int nt = 0; nt < 4; nt++) {
                int c0 = wn2 * 32 + nt * 8 + 2 * tig;
                #pragma unroll
                for (int e = 0; e < 4; e++) {
                    int i = (e < 2) ? i0 : i1;
                    int c = c0 + (e & 1);
                    float v = sf[nt][e] * SCALE;
                    if (i < 49 && c < 49) {
                        int ri = i / 7, ci = i - ri * 7;
                        int rj = c / 7, cj = c - rj * 7;
                        v += rpbs[(ri - rj + 6) * 13 + (ci - cj + 6)];
                        if (gidm[i] != gidm[c]) v -= 100.f;
                    }
                    Ssm[i][c] = v;
                }
            }
        }
        __syncthreads();

        // ---- softmax rows, write P bf16 (cols 49..63 zeroed) ----
        for (int r = wid; r < 49; r += 8) {
            float v0 = Ssm[r][lane];
            float v1 = (lane + 32 < 49) ? Ssm[r][lane + 32] : -1e30f;
            float m = fmaxf(v0, v1);
            #pragma unroll
            for (int o = 16; o; o >>= 1) m = fmaxf(m, __shfl_xor_sync(0xffffffffu, m, o));
            float e0 = __expf(v0 - m);
            float e1 = (lane + 32 < 49) ? __expf(v1 - m) : 0.f;
            float s = e0 + e1;
            #pragma unroll
            for (int o = 16; o; o >>= 1) s += __shfl_xor_sync(0xffffffffu, s, o);
            float inv = __fdividef(1.0f, s);
            Ps[r][lane]      = __float2bfloat16_rn(e0 * inv);
            Ps[r][lane + 32] = __float2bfloat16_rn(e1 * inv);
        }
        __syncthreads();

        // ---- O = P V : warps 4m x 2n(16), K=64 ----
        {
            int m = wid & 3, ng = wid >> 2;
            float of[2][4];
            #pragma unroll
            for (int t = 0; t < 2; t++)
                #pragma unroll
                for (int e = 0; e < 4; e++) of[t][e] = 0.f;
            #pragma unroll
            for (int ks = 0; ks < 4; ks++) {
                uint32_t a[4], b[2][2];
                const bf16* p0 = &Ps[m * 16 + g][ks * 16 + 2 * tig];
                a[0] = *(const uint32_t*)p0;
                a[1] = *(const uint32_t*)(p0 + 8 * 72);
                a[2] = *(const uint32_t*)(p0 + 8);
                a[3] = *(const uint32_t*)(p0 + 8 * 72 + 8);
                #pragma unroll
                for (int t = 0; t < 2; t++) {
                    const bf16* p = &Vt[ng * 16 + t * 8 + g][ks * 16 + 2 * tig];
                    b[t][0] = *(const uint32_t*)p;
                    b[t][1] = *(const uint32_t*)(p + 8);
                }
                #pragma unroll
                for (int t = 0; t < 2; t++) mma_bf16(of[t], a, b[t]);
            }
            int i0 = m * 16 + g, i1 = i0 + 8;
            #pragma unroll
            for (int t = 0; t < 2; t++) {
                int c = ng * 16 + t * 8 + 2 * tig;
                if (i0 < 49) {
                    bf16* o = g_attnob + (size_t)(win * NTOK + i0) * Cdim + h * HDIM + c;
                    *(bf162*)o = __floats2bfloat162_rn(of[t][0], of[t][1]);
                }
                if (i1 < 49) {
                    bf16* o = g_attnob + (size_t)(win * NTOK + i1) * Cdim + h * HDIM + c;
                    *(bf162*)o = __floats2bfloat162_rn(of[t][2], of[t][3]);
                }
            }
        }
    }
}

// ------------------------------ launcher -----------------------------------
#define SM3 (2 * (128 + 96) * SROW * 2)                    // 64512 B
#define SM6 (2 * (128 + 192) * SROW * 2 + 4096)            // 96256 B

extern "C" void kernel_launch(void* const* d_in, const int* in_sizes, int n_in,
                              void* d_out, int out_size) {
    const float* x      = (const float*)d_in[0];
    const float* qkv_w  = (const float*)d_in[1];
    const float* qkv_b  = (const float*)d_in[2];
    const float* proj_w = (const float*)d_in[3];
    const float* proj_b = (const float*)d_in[4];
    const float* rpb    = (const float*)d_in[5];
    const float* ln1_g  = (const float*)d_in[6];
    const float* ln1_b  = (const float*)d_in[7];
    const float* ln2_g  = (const float*)d_in[8];
    const float* ln2_b  = (const float*)d_in[9];
    const float* w1     = (const float*)d_in[10];
    const float* b1     = (const float*)d_in[11];
    const float* w2     = (const float*)d_in[12];
    const float* b2     = (const float*)d_in[13];
    float* out = (float*)d_out;

    bf16 *p_win, *p_qkv, *p_attno, *p_ln2, *p_hid;
    bf16 *p_qkvwT, *p_projwT, *p_w1T, *p_w2T;
    float *p_h;
    cudaGetSymbolAddress((void**)&p_win,    g_winb);
    cudaGetSymbolAddress((void**)&p_qkv,    g_qkvb);
    cudaGetSymbolAddress((void**)&p_attno,  g_attnob);
    cudaGetSymbolAddress((void**)&p_h,      g_h);
    cudaGetSymbolAddress((void**)&p_ln2,    g_ln2b);
    cudaGetSymbolAddress((void**)&p_hid,    g_hidb);
    cudaGetSymbolAddress((void**)&p_qkvwT,  g_qkvwT);
    cudaGetSymbolAddress((void**)&p_projwT, g_projwT);
    cudaGetSymbolAddress((void**)&p_w1T,    g_w1T);
    cudaGetSymbolAddress((void**)&p_w2T,    g_w2T);

    cudaFuncSetAttribute(tc_gemm<0,3,true>,  cudaFuncAttributeMaxDynamicSharedMemorySize, SM3);
    cudaFuncSetAttribute(tc_gemm<1,3,true>,  cudaFuncAttributeMaxDynamicSharedMemorySize, SM3);
    cudaFuncSetAttribute(tc_gemm<2,6,false>, cudaFuncAttributeMaxDynamicSharedMemorySize, SM6);
    cudaFuncSetAttribute(tc_gemm<3,3,false>, cudaFuncAttributeMaxDynamicSharedMemorySize, SM3);

    // 0. all weight transposes (fp32 -> bf16, K-major)
    transpose_all<<<dim3(24, 24, 4), dim3(32, 8)>>>(qkv_w, proj_w, w1, w2,
                                                    p_qkvwT, p_projwT, p_w1T, p_w2T);

    // 1. LN1 + shifted-window partition -> bf16
    ln_kernel<<<MROWS / 8, 256>>>(x, ln1_g, ln1_b, p_win);

    // 2. QKV: (100352,192) @ (192,576) -> bf16
    tc_gemm<0,3,true><<<dim3(MROWS / 128, 6), 256, SM3>>>(
        p_win, p_qkvwT, qkv_b, p_qkv, 576, 192, nullptr, nullptr, nullptr, nullptr);

    // 3. windowed attention (tensor cores) -> bf16
    attn_kernel<<<NWIN, 256>>>(rpb);

    // 4. proj + window-reverse + residual(x) + fused LN2 (g_h fp32, g_ln2 bf16)
    tc_gemm<2,6,false><<<dim3(MROWS / 128, 1), 256, SM6>>>(
        p_attno, p_projwT, proj_b, p_h, 192, 192, x, p_ln2, ln2_g, ln2_b);

    // 5. MLP1 + GELU -> bf16
    tc_gemm<1,3,true><<<dim3(MROWS / 128, 8), 256, SM3>>>(
        p_ln2, p_w1T, b1, p_hid, HID, 192, nullptr, nullptr, nullptr, nullptr);

    // 6. MLP2 + residual(h) -> fp32 out
    tc_gemm<3,3,false><<<dim3(MROWS / 128, 2), 256, SM3>>>(
        p_hid, p_w2T, b2, out, 192, HID, p_h, nullptr, nullptr, nullptr);
}

// round 9
// speedup vs baseline: 3.2354x; 1.0953x over previous
#include <cuda_runtime.h>
#include <cuda_bf16.h>
#include <cstdint>

// ---------------------------------------------------------------------------
// SwinBlock: B=32, H=W=56, C=192, heads=6, head_dim=32, WS=7, SS=3, N=49
// bf16 mma.sync GEMMs (k64 chunks) + register-resident flash attention.
// ---------------------------------------------------------------------------

#define HW      56
#define Cdim    192
#define NHEADS  6
#define HDIM    32
#define WSZ     7
#define SSH     3
#define NTOK    49
#define NWIN    2048
#define MROWS   100352
#define HID     768
#define SCALE   0.17677669529663687f
#define SROW    72      // bf16 elems per smem row (64 data + 8 pad)

typedef __nv_bfloat16 bf16;
typedef __nv_bfloat162 bf162;

// -------------------------- scratch (device globals) -----------------------
__device__ __align__(16) bf16  g_winb [(size_t)MROWS * Cdim];
__device__ __align__(16) bf16  g_qkvb [(size_t)MROWS * 3 * Cdim];
__device__ __align__(16) bf16  g_attnob[(size_t)MROWS * Cdim];
__device__ __align__(16) float g_h    [(size_t)MROWS * Cdim];
__device__ __align__(16) bf16  g_ln2b [(size_t)MROWS * Cdim];
__device__ __align__(16) bf16  g_hidb [(size_t)MROWS * HID];
__device__ __align__(16) bf16  g_qkvwT[576 * 192];
__device__ __align__(16) bf16  g_projwT[192 * 192];
__device__ __align__(16) bf16  g_w1T  [HID * 192];
__device__ __align__(16) bf16  g_w2T  [192 * HID];

// ------------------------------ helpers ------------------------------------
__device__ __forceinline__ void cpasync16(bf16* dst, const bf16* src) {
    uint32_t d = (uint32_t)__cvta_generic_to_shared(dst);
    asm volatile("cp.async.cg.shared.global [%0], [%1], 16;" :: "r"(d), "l"(src));
}
#define CP_COMMIT() asm volatile("cp.async.commit_group;" ::: "memory")

__device__ __forceinline__ void mma_bf16(float* d, const uint32_t* a, const uint32_t* b) {
    asm volatile(
        "mma.sync.aligned.m16n8k16.row.col.f32.bf16.bf16.f32 "
        "{%0,%1,%2,%3}, {%4,%5,%6,%7}, {%8,%9}, {%0,%1,%2,%3};"
        : "+f"(d[0]), "+f"(d[1]), "+f"(d[2]), "+f"(d[3])
        : "r"(a[0]), "r"(a[1]), "r"(a[2]), "r"(a[3]), "r"(b[0]), "r"(b[1]));
}

__device__ __forceinline__ uint32_t pack_bf162(float lo, float hi) {
    bf162 t = __floats2bfloat162_rn(lo, hi);
    return *(uint32_t*)&t;
}

__device__ __forceinline__ int permrow(int rw) {
    int win = rw / NTOK, n = rw - win * NTOK;
    int b   = win >> 6, wi = win & 63;
    int wh  = wi >> 3,  ww = wi & 7;
    int i   = n / WSZ,  j  = n - i * WSZ;
    int hs  = wh * WSZ + i + SSH; if (hs >= HW) hs -= HW;
    int ws  = ww * WSZ + j + SSH; if (ws >= HW) ws -= HW;
    return b * (HW * HW) + hs * HW + ws;
}

// ------------------ merged weight transpose (fp32 -> bf16 T) ----------------
__global__ void transpose_all(const float* __restrict__ qkvw,
                              const float* __restrict__ projw,
                              const float* __restrict__ w1,
                              const float* __restrict__ w2,
                              bf16* __restrict__ o0, bf16* __restrict__ o1,
                              bf16* __restrict__ o2, bf16* __restrict__ o3) {
    __shared__ float t[32][33];
    const float* in; bf16* out; int R, C;
    switch (blockIdx.z) {
        case 0: in = qkvw;  out = o0; R = 192; C = 576; break;
        case 1: in = projw; out = o1; R = 192; C = 192; break;
        case 2: in = w1;    out = o2; R = 192; C = 768; break;
        default:in = w2;    out = o3; R = 768; C = 192; break;
    }
    int bx = blockIdx.x * 32, by = blockIdx.y * 32;
    if (bx >= C || by >= R) return;
    int x = threadIdx.x, y0 = threadIdx.y;
    #pragma unroll
    for (int j = 0; j < 32; j += 8)
        t[y0 + j][x] = in[(size_t)(by + y0 + j) * C + bx + x];
    __syncthreads();
    #pragma unroll
    for (int j = 0; j < 32; j += 8)
        out[(size_t)(bx + y0 + j) * R + by + x] = __float2bfloat16_rn(t[x][y0 + j]);
}

// ------------------------- LN1 (warp/row, permuted read) -------------------
__global__ __launch_bounds__(256)
void ln_kernel(const float* __restrict__ in, const float* __restrict__ gamma,
               const float* __restrict__ beta, bf16* __restrict__ out) {
    int wid = threadIdx.x >> 5, lane = threadIdx.x & 31;
    int row = blockIdx.x * 8 + wid;
    int src = permrow(row);
    const float* p = in + (size_t)src * Cdim;

    float v[6];
    #pragma unroll
    for (int j = 0; j < 3; j++) {
        float2 xv = *(const float2*)&p[2 * lane + 64 * j];
        v[2 * j] = xv.x; v[2 * j + 1] = xv.y;
    }
    float s = v[0] + v[1] + v[2] + v[3] + v[4] + v[5];
    #pragma unroll
    for (int o = 16; o; o >>= 1) s += __shfl_xor_sync(0xffffffffu, s, o);
    float mu = s * (1.0f / Cdim);
    float sq = 0.f;
    #pragma unroll
    for (int j = 0; j < 6; j++) { v[j] -= mu; sq += v[j] * v[j]; }
    #pragma unroll
    for (int o = 16; o; o >>= 1) sq += __shfl_xor_sync(0xffffffffu, sq, o);
    float inv = rsqrtf(sq * (1.0f / Cdim) + 1e-5f);

    bf16* q = out + (size_t)row * Cdim;
    #pragma unroll
    for (int j = 0; j < 3; j++) {
        int c = 2 * lane + 64 * j;
        float o0 = v[2 * j] * inv * gamma[c] + beta[c];
        float o1 = v[2 * j + 1] * inv * gamma[c + 1] + beta[c + 1];
        *(bf162*)(q + c) = __floats2bfloat162_rn(o0, o1);
    }
}

// --------------------------- bf16 mma.sync GEMM ----------------------------
template<int CTA_N>
__device__ __forceinline__ void gload(const bf16* __restrict__ A,
                                      const bf16* __restrict__ BT,
                                      bf16* As, bf16* Bs,
                                      int mBase, int nBase, int K, int k0, int tid) {
    #pragma unroll
    for (int i = 0; i < 4; i++) {
        int idx = tid + i * 256;
        int r = idx >> 3, ch = idx & 7;
        cpasync16(As + r * SROW + ch * 8, A + (size_t)(mBase + r) * K + k0 + ch * 8);
    }
    #pragma unroll
    for (int i = 0; i < CTA_N * 8; i += 256) {
        int idx = tid + i;
        int r = idx >> 3, ch = idx & 7;
        cpasync16(Bs + r * SROW + ch * 8, BT + (size_t)(nBase + r) * K + k0 + ch * 8);
    }
    CP_COMMIT();
}

template<int EPI, int NT, bool OBF16>
__global__ __launch_bounds__(256)
void tc_gemm(const bf16* __restrict__ A, const bf16* __restrict__ BT,
             const float* __restrict__ bias, void* __restrict__ Cv,
             int N, int K, const float* __restrict__ resid,
             bf16* __restrict__ C2, const float* __restrict__ g2,
             const float* __restrict__ b2v) {
    constexpr int CTA_N = NT * 32;
    extern __shared__ __align__(16) bf16 sm[];
    bf16* AsBase = sm;
    bf16* BsBase = sm + 2 * 128 * SROW;

    int tid  = threadIdx.x;
    int wid  = tid >> 5, lane = tid & 31;
    int g    = lane >> 2, tig = lane & 3;
    int wm   = wid & 1, wn = wid >> 1;
    int mBase = blockIdx.x * 128;
    int nBase = blockIdx.y * CTA_N;
    int nk = K >> 6;

    float acc[4][NT][4];
    #pragma unroll
    for (int mt = 0; mt < 4; mt++)
        #pragma unroll
        for (int nt = 0; nt < NT; nt++)
            #pragma unroll
            for (int e = 0; e < 4; e++) acc[mt][nt][e] = 0.f;

    gload<CTA_N>(A, BT, AsBase, BsBase, mBase, nBase, K, 0, tid);

    for (int kt = 0; kt < nk; kt++) {
        int buf = kt & 1;
        if (kt + 1 < nk) {
            gload<CTA_N>(A, BT, AsBase + (buf ^ 1) * 128 * SROW,
                         BsBase + (buf ^ 1) * CTA_N * SROW,
                         mBase, nBase, K, (kt + 1) << 6, tid);
            asm volatile("cp.async.wait_group 1;" ::: "memory");
        } else {
            asm volatile("cp.async.wait_group 0;" ::: "memory");
        }
        __syncthreads();

        const bf16* As = AsBase + buf * 128 * SROW;
        const bf16* Bs = BsBase + buf * CTA_N * SROW;

        #pragma unroll
        for (int s = 0; s < 4; s++) {
            uint32_t a[4][4], b[NT][2];
            #pragma unroll
            for (int mt = 0; mt < 4; mt++) {
                int r = wm * 64 + mt * 16 + g;
                const bf16* p0 = As + r * SROW + s * 16 + 2 * tig;
                const bf16* p1 = p0 + 8 * SROW;
                a[mt][0] = *(const uint32_t*)p0;
                a[mt][1] = *(const uint32_t*)p1;
                a[mt][2] = *(const uint32_t*)(p0 + 8);
                a[mt][3] = *(const uint32_t*)(p1 + 8);
            }
            #pragma unroll
            for (int nt = 0; nt < NT; nt++) {
                int n = wn * NT * 8 + nt * 8 + g;
                const bf16* p = Bs + n * SROW + s * 16 + 2 * tig;
                b[nt][0] = *(const uint32_t*)p;
                b[nt][1] = *(const uint32_t*)(p + 8);
            }
            #pragma unroll
            for (int mt = 0; mt < 4; mt++)
                #pragma unroll
                for (int nt = 0; nt < NT; nt++)
                    mma_bf16(acc[mt][nt], a[mt], b[nt]);
        }
        __syncthreads();
    }

    // ---------------- epilogue ----------------
    float* s_sum = (float*)(sm + 2 * (128 + CTA_N) * SROW);
    float* s_sq  = s_sum + 512;

    #pragma unroll
    for (int mt = 0; mt < 4; mt++) {
        int lr0 = wm * 64 + mt * 16 + g;
        int lr1 = lr0 + 8;
        int r0 = mBase + lr0, r1 = mBase + lr1;
        int p0 = r0, p1 = r1;
        if (EPI == 2) { p0 = permrow(r0); p1 = permrow(r1); }

        float s0 = 0.f, q0 = 0.f, s1 = 0.f, q1 = 0.f;
        #pragma unroll
        for (int nt = 0; nt < NT; nt++) {
            int c = nBase + wn * NT * 8 + nt * 8 + 2 * tig;
            float2 bv = *(const float2*)(bias + c);
            float v0 = acc[mt][nt][0] + bv.x;
            float v1 = acc[mt][nt][1] + bv.y;
            float v2 = acc[mt][nt][2] + bv.x;
            float v3 = acc[mt][nt][3] + bv.y;
            if (EPI == 1) {
                v0 = 0.5f * v0 * (1.0f + erff(v0 * 0.70710678118654752f));
                v1 = 0.5f * v1 * (1.0f + erff(v1 * 0.70710678118654752f));
                v2 = 0.5f * v2 * (1.0f + erff(v2 * 0.70710678118654752f));
                v3 = 0.5f * v3 * (1.0f + erff(v3 * 0.70710678118654752f));
            } else if (EPI == 2) {
                float2 ra = *(const float2*)(resid + (size_t)p0 * Cdim + c);
                float2 rb = *(const float2*)(resid + (size_t)p1 * Cdim + c);
                v0 += ra.x; v1 += ra.y; v2 += rb.x; v3 += rb.y;
                s0 += v0 + v1; q0 += v0 * v0 + v1 * v1;
                s1 += v2 + v3; q1 += v2 * v2 + v3 * v3;
                acc[mt][nt][0] = v0; acc[mt][nt][1] = v1;
                acc[mt][nt][2] = v2; acc[mt][nt][3] = v3;
            } else if (EPI == 3) {
                float2 ra = *(const float2*)(resid + (size_t)r0 * Cdim + c);
                float2 rb = *(const float2*)(resid + (size_t)r1 * Cdim + c);
                v0 += ra.x; v1 += ra.y; v2 += rb.x; v3 += rb.y;
            }
            if (OBF16) {
                bf16* Cb = (bf16*)Cv;
                *(bf162*)(Cb + (size_t)p0 * N + c) = __floats2bfloat162_rn(v0, v1);
                *(bf162*)(Cb + (size_t)p1 * N + c) = __floats2bfloat162_rn(v2, v3);
            } else {
                float* Cf = (float*)Cv;
                *(float2*)(Cf + (size_t)p0 * N + c) = make_float2(v0, v1);
                *(float2*)(Cf + (size_t)p1 * N + c) = make_float2(v2, v3);
            }
        }
        if (EPI == 2) {
            #pragma unroll
            for (int o = 1; o < 4; o <<= 1) {
                s0 += __shfl_xor_sync(0xffffffffu, s0, o);
                q0 += __shfl_xor_sync(0xffffffffu, q0, o);
                s1 += __shfl_xor_sync(0xffffffffu, s1, o);
                q1 += __shfl_xor_sync(0xffffffffu, q1, o);
            }
            if (tig == 0) {
                s_sum[wn * 128 + lr0] = s0;  s_sq[wn * 128 + lr0] = q0;
                s_sum[wn * 128 + lr1] = s1;  s_sq[wn * 128 + lr1] = q1;
            }
        }
    }

    if (EPI == 2) {
        __syncthreads();
        #pragma unroll
        for (int mt = 0; mt < 4; mt++) {
            int lr0 = wm * 64 + mt * 16 + g;
            int lr1 = lr0 + 8;
            int p0 = permrow(mBase + lr0), p1 = permrow(mBase + lr1);
            float su0 = s_sum[lr0] + s_sum[128 + lr0] + s_sum[256 + lr0] + s_sum[384 + lr0];
            float sq0 = s_sq[lr0]  + s_sq[128 + lr0]  + s_sq[256 + lr0]  + s_sq[384 + lr0];
            float su1 = s_sum[lr1] + s_sum[128 + lr1] + s_sum[256 + lr1] + s_sum[384 + lr1];
            float sq1 = s_sq[lr1]  + s_sq[128 + lr1]  + s_sq[256 + lr1]  + s_sq[384 + lr1];
            float mu0 = su0 * (1.0f / Cdim);
            float mu1 = su1 * (1.0f / Cdim);
            float iv0 = rsqrtf(sq0 * (1.0f / Cdim) - mu0 * mu0 + 1e-5f);
            float iv1 = rsqrtf(sq1 * (1.0f / Cdim) - mu1 * mu1 + 1e-5f);
            #pragma unroll
            for (int nt = 0; nt < NT; nt++) {
                int c = wn * NT * 8 + nt * 8 + 2 * tig;
                float2 gv = *(const float2*)(g2 + c);
                float2 bb = *(const float2*)(b2v + c);
                float o0 = (acc[mt][nt][0] - mu0) * iv0 * gv.x + bb.x;
                float o1 = (acc[mt][nt][1] - mu0) * iv0 * gv.y + bb.y;
                float o2 = (acc[mt][nt][2] - mu1) * iv1 * gv.x + bb.x;
                float o3 = (acc[mt][nt][3] - mu1) * iv1 * gv.y + bb.y;
                *(bf162*)(C2 + (size_t)p0 * Cdim + c) = __floats2bfloat162_rn(o0, o1);
                *(bf162*)(C2 + (size_t)p1 * Cdim + c) = __floats2bfloat162_rn(o2, o3);
            }
        }
    }
}

// ------------------- register-resident flash attention ---------------------
// one block per window; 8 warps = 2 heads x 4 row-groups; 3 head-pair iters.
// S warp tile m16 x n64 -> softmax in registers -> P packed into A frags.
__global__ __launch_bounds__(256)
void attn_kernel(const float* __restrict__ rpb_table) {
    __shared__ __align__(16) bf16 Qs[2][64][40];
    __shared__ __align__(16) bf16 Ks[2][64][40];
    __shared__ __align__(16) bf16 Vt[2][32][72];   // [head][d][token]
    __shared__ float rpbs[2][169];
    __shared__ int   gidm[64];

    int win = blockIdx.x;
    int tid = threadIdx.x;
    int wid = tid >> 5, lane = tid & 31;
    int g = lane >> 2, tig = lane & 3;
    int hsel = wid >> 2, wm2 = wid & 3;
    int wi = win & 63;
    int wh = wi >> 3, ww = wi & 7;

    if (tid < 64) {
        int v = -1;
        if (tid < 49) {
            int ri = tid / 7, ci = tid - ri * 7;
            int hi = wh * 7 + ri, wc = ww * 7 + ci;
            v = (hi < 49 ? 0 : (hi < 53 ? 1 : 2)) * 3 + (wc < 49 ? 0 : (wc < 53 ? 1 : 2));
        }
        gidm[tid] = v;
    }
    // zero V token-pad region (tokens 49..63), both head slots, once
    for (int idx = tid; idx < 2 * 32 * 15; idx += 256) {
        int hh = idx / 480, rem = idx - hh * 480;
        int d = rem / 15, n = 49 + rem - (rem / 15) * 15;
        Vt[hh][d][n] = __float2bfloat16(0.f);
    }

    const bf16* base = g_qkvb + (size_t)win * NTOK * 576;

    for (int it = 0; it < 3; it++) {
        int h0 = it * 2;
        __syncthreads();
        // rpb rows for both heads
        for (int idx = tid; idx < 338; idx += 256) {
            int hh = idx / 169, e = idx - hh * 169;
            rpbs[hh][e] = rpb_table[e * NHEADS + h0 + hh];
        }
        // Q, K: 49 tokens x (2 heads x 2 mats x 4 chunks)
        for (int idx = tid; idx < 784; idx += 256) {
            int n = idx >> 4, sub = idx & 15;
            int hh = sub >> 3, mat = (sub >> 2) & 1, ch = sub & 3;
            uint4 v = *(const uint4*)(base + (size_t)n * 576 + mat * 192 + (h0 + hh) * 32 + ch * 8);
            *(uint4*)(&(mat ? Ks : Qs)[hh][n][ch * 8]) = v;
        }
        // V transposed
        for (int idx = tid; idx < 392; idx += 256) {
            int n = idx >> 3, hh = (idx >> 2) & 1, ch = idx & 3;
            uint4 v = *(const uint4*)(base + (size_t)n * 576 + 384 + (h0 + hh) * 32 + ch * 8);
            bf16 tmp[8]; *(uint4*)tmp = v;
            #pragma unroll
            for (int e = 0; e < 8; e++) Vt[hh][ch * 8 + e][n] = tmp[e];
        }
        __syncthreads();

        // ---- S = Q K^T : this warp covers rows {r0, r0+8} x all 64 cols ----
        int r0 = wm2 * 16 + g, r1 = r0 + 8;
        float sf[8][4];
        #pragma unroll
        for (int j = 0; j < 8; j++)
            #pragma unroll
            for (int e = 0; e < 4; e++) sf[j][e] = 0.f;

        #pragma unroll
        for (int s = 0; s < 2; s++) {
            uint32_t a[4];
            const bf16* p0 = &Qs[hsel][r0][s * 16 + 2 * tig];
            a[0] = *(const uint32_t*)p0;
            a[1] = *(const uint32_t*)(p0 + 8 * 40);
            a[2] = *(const uint32_t*)(p0 + 8);
            a[3] = *(const uint32_t*)(p0 + 8 * 40 + 8);
            #pragma unroll
            for (int j = 0; j < 8; j++) {
                uint32_t b[2];
                const bf16* p = &Ks[hsel][j * 8 + g][s * 16 + 2 * tig];
                b[0] = *(const uint32_t*)p;
                b[1] = *(const uint32_t*)(p + 8);
                mma_bf16(sf[j], a, b);
            }
        }

        // ---- scale + rpb + shift-mask (rows/cols >= 49 -> -1e30) ----
        int gid0 = gidm[r0 < 64 ? r0 : 0];
        int gid1 = gidm[r1 < 64 ? r1 : 0];
        int ri0 = r0 / 7, ci0 = r0 - ri0 * 7;
        int ri1 = r1 / 7, ci1 = r1 - ri1 * 7;
        #pragma unroll
        for (int j = 0; j < 8; j++) {
            int c0 = j * 8 + 2 * tig;
            #pragma unroll
            for (int e = 0; e < 4; e++) {
                int r  = (e < 2) ? r0 : r1;
                int gid = (e < 2) ? gid0 : gid1;
                int ri = (e < 2) ? ri0 : ri1, ci = (e < 2) ? ci0 : ci1;
                int c = c0 + (e & 1);
                float v;
                if (r < 49 && c < 49) {
                    int rj = c / 7, cj = c - rj * 7;
                    v = sf[j][e] * SCALE + rpbs[hsel][(ri - rj + 6) * 13 + (ci - cj + 6)];
                    if (gid != gidm[c]) v -= 100.f;
                } else {
                    v = -1e30f;
                }
                sf[j][e] = v;
            }
        }

        // ---- softmax in registers (reduce across quad: shfl 1,2) ----
        float m0 = -1e30f, m1 = -1e30f;
        #pragma unroll
        for (int j = 0; j < 8; j++) {
            m0 = fmaxf(m0, fmaxf(sf[j][0], sf[j][1]));
            m1 = fmaxf(m1, fmaxf(sf[j][2], sf[j][3]));
        }
        m0 = fmaxf(m0, __shfl_xor_sync(0xffffffffu, m0, 1));
        m0 = fmaxf(m0, __shfl_xor_sync(0xffffffffu, m0, 2));
        m1 = fmaxf(m1, __shfl_xor_sync(0xffffffffu, m1, 1));
        m1 = fmaxf(m1, __shfl_xor_sync(0xffffffffu, m1, 2));
        float s0 = 0.f, s1 = 0.f;
        #pragma unroll
        for (int j = 0; j < 8; j++) {
            sf[j][0] = __expf(sf[j][0] - m0); s0 += sf[j][0];
            sf[j][1] = __expf(sf[j][1] - m0); s0 += sf[j][1];
            sf[j][2] = __expf(sf[j][2] - m1); s1 += sf[j][2];
            sf[j][3] = __expf(sf[j][3] - m1); s1 += sf[j][3];
        }
        s0 += __shfl_xor_sync(0xffffffffu, s0, 1);
        s0 += __shfl_xor_sync(0xffffffffu, s0, 2);
        s1 += __shfl_xor_sync(0xffffffffu, s1, 1);
        s1 += __shfl_xor_sync(0xffffffffu, s1, 2);
        float inv0 = __fdividef(1.0f, s0);
        float inv1 = __fdividef(1.0f, s1);

        // ---- pack P into A fragments directly from accumulators ----
        uint32_t pa[4][4];
        #pragma unroll
        for (int ks = 0; ks < 4; ks++) {
            pa[ks][0] = pack_bf162(sf[2 * ks][0] * inv0, sf[2 * ks][1] * inv0);
            pa[ks][1] = pack_bf162(sf[2 * ks][2] * inv1, sf[2 * ks][3] * inv1);
            pa[ks][2] = pack_bf162(sf[2 * ks + 1][0] * inv0, sf[2 * ks + 1][1] * inv0);
            pa[ks][3] = pack_bf162(sf[2 * ks + 1][2] * inv1, sf[2 * ks + 1][3] * inv1);
        }

        // ---- O = P V ----
        float of[4][4];
        #pragma unroll
        for (int t = 0; t < 4; t++)
            #pragma unroll
            for (int e = 0; e < 4; e++) of[t][e] = 0.f;
        #pragma unroll
        for (int ks = 0; ks < 4; ks++) {
            #pragma unroll
            for (int t = 0; t < 4; t++) {
                uint32_t b[2];
                const bf16* p = &Vt[hsel][t * 8 + g][ks * 16 + 2 * tig];
                b[0] = *(const uint32_t*)p;
                b[1] = *(const uint32_t*)(p + 8);
                mma_bf16(of[t], pa[ks], b);
            }
        }

        // ---- store O ----
        int h = h0 + hsel;
        #pragma unroll
        for (int t = 0; t < 4; t++) {
            int c = t * 8 + 2 * tig;
            if (r0 < 49) {
                bf16* o = g_attnob + (size_t)(win * NTOK + r0) * Cdim + h * HDIM + c;
                *(bf162*)o = __floats2bfloat162_rn(of[t][0], of[t][1]);
            }
            if (r1 < 49) {
                bf16* o = g_attnob + (size_t)(win * NTOK + r1) * Cdim + h * HDIM + c;
                *(bf162*)o = __floats2bfloat162_rn(of[t][2], of[t][3]);
            }
        }
    }
}

// ------------------------------ launcher -----------------------------------
#define SM3 (2 * (128 + 96) * SROW * 2)                    // 64512 B
#define SM6 (2 * (128 + 192) * SROW * 2 + 4096)            // 96256 B

extern "C" void kernel_launch(void* const* d_in, const int* in_sizes, int n_in,
                              void* d_out, int out_size) {
    const float* x      = (const float*)d_in[0];
    const float* qkv_w  = (const float*)d_in[1];
    const float* qkv_b  = (const float*)d_in[2];
    const float* proj_w = (const float*)d_in[3];
    const float* proj_b = (const float*)d_in[4];
    const float* rpb    = (const float*)d_in[5];
    const float* ln1_g  = (const float*)d_in[6];
    const float* ln1_b  = (const float*)d_in[7];
    const float* ln2_g  = (const float*)d_in[8];
    const float* ln2_b  = (const float*)d_in[9];
    const float* w1     = (const float*)d_in[10];
    const float* b1     = (const float*)d_in[11];
    const float* w2     = (const float*)d_in[12];
    const float* b2     = (const float*)d_in[13];
    float* out = (float*)d_out;

    bf16 *p_win, *p_qkv, *p_attno, *p_ln2, *p_hid;
    bf16 *p_qkvwT, *p_projwT, *p_w1T, *p_w2T;
    float *p_h;
    cudaGetSymbolAddress((void**)&p_win,    g_winb);
    cudaGetSymbolAddress((void**)&p_qkv,    g_qkvb);
    cudaGetSymbolAddress((void**)&p_attno,  g_attnob);
    cudaGetSymbolAddress((void**)&p_h,      g_h);
    cudaGetSymbolAddress((void**)&p_ln2,    g_ln2b);
    cudaGetSymbolAddress((void**)&p_hid,    g_hidb);
    cudaGetSymbolAddress((void**)&p_qkvwT,  g_qkvwT);
    cudaGetSymbolAddress((void**)&p_projwT, g_projwT);
    cudaGetSymbolAddress((void**)&p_w1T,    g_w1T);
    cudaGetSymbolAddress((void**)&p_w2T,    g_w2T);

    cudaFuncSetAttribute(tc_gemm<0,3,true>,  cudaFuncAttributeMaxDynamicSharedMemorySize, SM3);
    cudaFuncSetAttribute(tc_gemm<1,3,true>,  cudaFuncAttributeMaxDynamicSharedMemorySize, SM3);
    cudaFuncSetAttribute(tc_gemm<2,6,false>, cudaFuncAttributeMaxDynamicSharedMemorySize, SM6);
    cudaFuncSetAttribute(tc_gemm<3,3,false>, cudaFuncAttributeMaxDynamicSharedMemorySize, SM3);

    // 0. all weight transposes (fp32 -> bf16, K-major)
    transpose_all<<<dim3(24, 24, 4), dim3(32, 8)>>>(qkv_w, proj_w, w1, w2,
                                                    p_qkvwT, p_projwT, p_w1T, p_w2T);

    // 1. LN1 + shifted-window partition -> bf16
    ln_kernel<<<MROWS / 8, 256>>>(x, ln1_g, ln1_b, p_win);

    // 2. QKV: (100352,192) @ (192,576) -> bf16
    tc_gemm<0,3,true><<<dim3(MROWS / 128, 6), 256, SM3>>>(
        p_win, p_qkvwT, qkv_b, p_qkv, 576, 192, nullptr, nullptr, nullptr, nullptr);

    // 3. windowed attention (register flash) -> bf16
    attn_kernel<<<NWIN, 256>>>(rpb);

    // 4. proj + window-reverse + residual(x) + fused LN2 (g_h fp32, g_ln2 bf16)
    tc_gemm<2,6,false><<<dim3(MROWS / 128, 1), 256, SM6>>>(
        p_attno, p_projwT, proj_b, p_h, 192, 192, x, p_ln2, ln2_g, ln2_b);

    // 5. MLP1 + GELU -> bf16
    tc_gemm<1,3,true><<<dim3(MROWS / 128, 8), 256, SM3>>>(
        p_ln2, p_w1T, b1, p_hid, HID, 192, nullptr, nullptr, nullptr, nullptr);

    // 6. MLP2 + residual(h) -> fp32 out
    tc_gemm<3,3,false><<<dim3(MROWS / 128, 2), 256, SM3>>>(
        p_hid, p_w2T, b2, out, 192, HID, p_h, nullptr, nullptr, nullptr);
}

// round 10
// speedup vs baseline: 3.2742x; 1.0120x over previous
#include <cuda_runtime.h>
#include <cuda_bf16.h>
#include <cstdint>

// ---------------------------------------------------------------------------
// SwinBlock: B=32, H=W=56, C=192, heads=6, head_dim=32, WS=7, SS=3, N=49
// bf16 mma.sync GEMMs (ldmatrix frags, k64 chunks) + register flash attention.
// ---------------------------------------------------------------------------

#define HW      56
#define Cdim    192
#define NHEADS  6
#define HDIM    32
#define WSZ     7
#define SSH     3
#define NTOK    49
#define NWIN    2048
#define MROWS   100352
#define HID     768
#define SCALE   0.17677669529663687f
#define SROW    72      // bf16 elems per smem row (64 data + 8 pad)

typedef __nv_bfloat16 bf16;
typedef __nv_bfloat162 bf162;

// -------------------------- scratch (device globals) -----------------------
__device__ __align__(16) bf16  g_winb [(size_t)MROWS * Cdim];
__device__ __align__(16) bf16  g_qkvb [(size_t)MROWS * 3 * Cdim];
__device__ __align__(16) bf16  g_attnob[(size_t)MROWS * Cdim];
__device__ __align__(16) float g_h    [(size_t)MROWS * Cdim];
__device__ __align__(16) bf16  g_ln2b [(size_t)MROWS * Cdim];
__device__ __align__(16) bf16  g_hidb [(size_t)MROWS * HID];
__device__ __align__(16) bf16  g_qkvwT[576 * 192];
__device__ __align__(16) bf16  g_projwT[192 * 192];
__device__ __align__(16) bf16  g_w1T  [HID * 192];
__device__ __align__(16) bf16  g_w2T  [192 * HID];

// ------------------------------ helpers ------------------------------------
__device__ __forceinline__ void cpasync16(bf16* dst, const bf16* src) {
    uint32_t d = (uint32_t)__cvta_generic_to_shared(dst);
    asm volatile("cp.async.cg.shared.global [%0], [%1], 16;" :: "r"(d), "l"(src));
}
#define CP_COMMIT() asm volatile("cp.async.commit_group;" ::: "memory")

__device__ __forceinline__ void mma_bf16(float* d, const uint32_t* a, const uint32_t* b) {
    asm volatile(
        "mma.sync.aligned.m16n8k16.row.col.f32.bf16.bf16.f32 "
        "{%0,%1,%2,%3}, {%4,%5,%6,%7}, {%8,%9}, {%0,%1,%2,%3};"
        : "+f"(d[0]), "+f"(d[1]), "+f"(d[2]), "+f"(d[3])
        : "r"(a[0]), "r"(a[1]), "r"(a[2]), "r"(a[3]), "r"(b[0]), "r"(b[1]));
}

__device__ __forceinline__ void ldsm_x4(uint32_t* r, uint32_t addr) {
    asm volatile("ldmatrix.sync.aligned.m8n8.x4.shared.b16 {%0,%1,%2,%3}, [%4];"
        : "=r"(r[0]), "=r"(r[1]), "=r"(r[2]), "=r"(r[3]) : "r"(addr));
}
__device__ __forceinline__ void ldsm_x2(uint32_t* r, uint32_t addr) {
    asm volatile("ldmatrix.sync.aligned.m8n8.x2.shared.b16 {%0,%1}, [%2];"
        : "=r"(r[0]), "=r"(r[1]) : "r"(addr));
}

__device__ __forceinline__ uint32_t pack_bf162(float lo, float hi) {
    bf162 t = __floats2bfloat162_rn(lo, hi);
    return *(uint32_t*)&t;
}

__device__ __forceinline__ int permrow(int rw) {
    int win = rw / NTOK, n = rw - win * NTOK;
    int b   = win >> 6, wi = win & 63;
    int wh  = wi >> 3,  ww = wi & 7;
    int i   = n / WSZ,  j  = n - i * WSZ;
    int hs  = wh * WSZ + i + SSH; if (hs >= HW) hs -= HW;
    int ws  = ww * WSZ + j + SSH; if (ws >= HW) ws -= HW;
    return b * (HW * HW) + hs * HW + ws;
}

// ------------------ merged weight transpose (fp32 -> bf16 T) ----------------
__global__ void transpose_all(const float* __restrict__ qkvw,
                              const float* __restrict__ projw,
                              const float* __restrict__ w1,
                              const float* __restrict__ w2,
                              bf16* __restrict__ o0, bf16* __restrict__ o1,
                              bf16* __restrict__ o2, bf16* __restrict__ o3) {
    __shared__ float t[32][33];
    const float* in; bf16* out; int R, C;
    switch (blockIdx.z) {
        case 0: in = qkvw;  out = o0; R = 192; C = 576; break;
        case 1: in = projw; out = o1; R = 192; C = 192; break;
        case 2: in = w1;    out = o2; R = 192; C = 768; break;
        default:in = w2;    out = o3; R = 768; C = 192; break;
    }
    int bx = blockIdx.x * 32, by = blockIdx.y * 32;
    if (bx >= C || by >= R) return;
    int x = threadIdx.x, y0 = threadIdx.y;
    #pragma unroll
    for (int j = 0; j < 32; j += 8)
        t[y0 + j][x] = in[(size_t)(by + y0 + j) * C + bx + x];
    __syncthreads();
    #pragma unroll
    for (int j = 0; j < 32; j += 8)
        out[(size_t)(bx + y0 + j) * R + by + x] = __float2bfloat16_rn(t[x][y0 + j]);
}

// ------------------------- LN1 (warp/row, permuted read) -------------------
__global__ __launch_bounds__(256)
void ln_kernel(const float* __restrict__ in, const float* __restrict__ gamma,
               const float* __restrict__ beta, bf16* __restrict__ out) {
    int wid = threadIdx.x >> 5, lane = threadIdx.x & 31;
    int row = blockIdx.x * 8 + wid;
    int src = permrow(row);
    const float* p = in + (size_t)src * Cdim;

    float v[6];
    #pragma unroll
    for (int j = 0; j < 3; j++) {
        float2 xv = *(const float2*)&p[2 * lane + 64 * j];
        v[2 * j] = xv.x; v[2 * j + 1] = xv.y;
    }
    float s = v[0] + v[1] + v[2] + v[3] + v[4] + v[5];
    #pragma unroll
    for (int o = 16; o; o >>= 1) s += __shfl_xor_sync(0xffffffffu, s, o);
    float mu = s * (1.0f / Cdim);
    float sq = 0.f;
    #pragma unroll
    for (int j = 0; j < 6; j++) { v[j] -= mu; sq += v[j] * v[j]; }
    #pragma unroll
    for (int o = 16; o; o >>= 1) sq += __shfl_xor_sync(0xffffffffu, sq, o);
    float inv = rsqrtf(sq * (1.0f / Cdim) + 1e-5f);

    bf16* q = out + (size_t)row * Cdim;
    #pragma unroll
    for (int j = 0; j < 3; j++) {
        int c = 2 * lane + 64 * j;
        float o0 = v[2 * j] * inv * gamma[c] + beta[c];
        float o1 = v[2 * j + 1] * inv * gamma[c + 1] + beta[c + 1];
        *(bf162*)(q + c) = __floats2bfloat162_rn(o0, o1);
    }
}

// --------------------------- bf16 mma.sync GEMM ----------------------------
template<int CTA_N>
__device__ __forceinline__ void gload(const bf16* __restrict__ A,
                                      const bf16* __restrict__ BT,
                                      bf16* As, bf16* Bs,
                                      int mBase, int nBase, int K, int k0, int tid) {
    #pragma unroll
    for (int i = 0; i < 4; i++) {
        int idx = tid + i * 256;
        int r = idx >> 3, ch = idx & 7;
        cpasync16(As + r * SROW + ch * 8, A + (size_t)(mBase + r) * K + k0 + ch * 8);
    }
    #pragma unroll
    for (int i = 0; i < CTA_N * 8; i += 256) {
        int idx = tid + i;
        int r = idx >> 3, ch = idx & 7;
        cpasync16(Bs + r * SROW + ch * 8, BT + (size_t)(nBase + r) * K + k0 + ch * 8);
    }
    CP_COMMIT();
}

template<int EPI, int NT, bool OBF16>
__global__ __launch_bounds__(256)
void tc_gemm(const bf16* __restrict__ A, const bf16* __restrict__ BT,
             const float* __restrict__ bias, void* __restrict__ Cv,
             int N, int K, const float* __restrict__ resid,
             bf16* __restrict__ C2, const float* __restrict__ g2,
             const float* __restrict__ b2v) {
    constexpr int CTA_N = NT * 32;
    extern __shared__ __align__(16) bf16 sm[];
    bf16* AsBase = sm;
    bf16* BsBase = sm + 2 * 128 * SROW;

    int tid  = threadIdx.x;
    int wid  = tid >> 5, lane = tid & 31;
    int g    = lane >> 2, tig = lane & 3;
    int wm   = wid & 1, wn = wid >> 1;
    int mBase = blockIdx.x * 128;
    int nBase = blockIdx.y * CTA_N;
    int nk = K >> 6;

    // ldmatrix lane addressing (byte offsets added later)
    int aRow = wm * 64 + (lane & 15);
    int aCol = (lane >> 4) << 3;
    int bRow = wn * NT * 8 + (lane & 7);
    int bCol = ((lane >> 3) & 1) << 3;

    float acc[4][NT][4];
    #pragma unroll
    for (int mt = 0; mt < 4; mt++)
        #pragma unroll
        for (int nt = 0; nt < NT; nt++)
            #pragma unroll
            for (int e = 0; e < 4; e++) acc[mt][nt][e] = 0.f;

    gload<CTA_N>(A, BT, AsBase, BsBase, mBase, nBase, K, 0, tid);

    for (int kt = 0; kt < nk; kt++) {
        int buf = kt & 1;
        if (kt + 1 < nk) {
            gload<CTA_N>(A, BT, AsBase + (buf ^ 1) * 128 * SROW,
                         BsBase + (buf ^ 1) * CTA_N * SROW,
                         mBase, nBase, K, (kt + 1) << 6, tid);
            asm volatile("cp.async.wait_group 1;" ::: "memory");
        } else {
            asm volatile("cp.async.wait_group 0;" ::: "memory");
        }
        __syncthreads();

        const bf16* As = AsBase + buf * 128 * SROW;
        const bf16* Bs = BsBase + buf * CTA_N * SROW;
        uint32_t aq = (uint32_t)__cvta_generic_to_shared(As + aRow * SROW + aCol);
        uint32_t bq = (uint32_t)__cvta_generic_to_shared(Bs + bRow * SROW + bCol);

        #pragma unroll
        for (int s = 0; s < 4; s++) {
            uint32_t a[4][4], b[NT][2];
            #pragma unroll
            for (int mt = 0; mt < 4; mt++)
                ldsm_x4(a[mt], aq + (mt * 16 * SROW + s * 16) * 2);
            #pragma unroll
            for (int nt = 0; nt < NT; nt++)
                ldsm_x2(b[nt], bq + (nt * 8 * SROW + s * 16) * 2);
            #pragma unroll
            for (int mt = 0; mt < 4; mt++)
                #pragma unroll
                for (int nt = 0; nt < NT; nt++)
                    mma_bf16(acc[mt][nt], a[mt], b[nt]);
        }
        __syncthreads();
    }

    // ---------------- epilogue ----------------
    float* s_sum = (float*)(sm + 2 * (128 + CTA_N) * SROW);
    float* s_sq  = s_sum + 512;

    #pragma unroll
    for (int mt = 0; mt < 4; mt++) {
        int lr0 = wm * 64 + mt * 16 + g;
        int lr1 = lr0 + 8;
        int r0 = mBase + lr0, r1 = mBase + lr1;
        int p0 = r0, p1 = r1;
        if (EPI == 2) { p0 = permrow(r0); p1 = permrow(r1); }

        float s0 = 0.f, q0 = 0.f, s1 = 0.f, q1 = 0.f;
        #pragma unroll
        for (int nt = 0; nt < NT; nt++) {
            int c = nBase + wn * NT * 8 + nt * 8 + 2 * tig;
            float2 bv = *(const float2*)(bias + c);
            float v0 = acc[mt][nt][0] + bv.x;
            float v1 = acc[mt][nt][1] + bv.y;
            float v2 = acc[mt][nt][2] + bv.x;
            float v3 = acc[mt][nt][3] + bv.y;
            if (EPI == 1) {
                v0 = 0.5f * v0 * (1.0f + erff(v0 * 0.70710678118654752f));
                v1 = 0.5f * v1 * (1.0f + erff(v1 * 0.70710678118654752f));
                v2 = 0.5f * v2 * (1.0f + erff(v2 * 0.70710678118654752f));
                v3 = 0.5f * v3 * (1.0f + erff(v3 * 0.70710678118654752f));
            } else if (EPI == 2) {
                float2 ra = *(const float2*)(resid + (size_t)p0 * Cdim + c);
                float2 rb = *(const float2*)(resid + (size_t)p1 * Cdim + c);
                v0 += ra.x; v1 += ra.y; v2 += rb.x; v3 += rb.y;
                s0 += v0 + v1; q0 += v0 * v0 + v1 * v1;
                s1 += v2 + v3; q1 += v2 * v2 + v3 * v3;
                acc[mt][nt][0] = v0; acc[mt][nt][1] = v1;
                acc[mt][nt][2] = v2; acc[mt][nt][3] = v3;
            } else if (EPI == 3) {
                float2 ra = *(const float2*)(resid + (size_t)r0 * Cdim + c);
                float2 rb = *(const float2*)(resid + (size_t)r1 * Cdim + c);
                v0 += ra.x; v1 += ra.y; v2 += rb.x; v3 += rb.y;
            }
            if (OBF16) {
                bf16* Cb = (bf16*)Cv;
                *(bf162*)(Cb + (size_t)p0 * N + c) = __floats2bfloat162_rn(v0, v1);
                *(bf162*)(Cb + (size_t)p1 * N + c) = __floats2bfloat162_rn(v2, v3);
            } else {
                float* Cf = (float*)Cv;
                *(float2*)(Cf + (size_t)p0 * N + c) = make_float2(v0, v1);
                *(float2*)(Cf + (size_t)p1 * N + c) = make_float2(v2, v3);
            }
        }
        if (EPI == 2) {
            #pragma unroll
            for (int o = 1; o < 4; o <<= 1) {
                s0 += __shfl_xor_sync(0xffffffffu, s0, o);
                q0 += __shfl_xor_sync(0xffffffffu, q0, o);
                s1 += __shfl_xor_sync(0xffffffffu, s1, o);
                q1 += __shfl_xor_sync(0xffffffffu, q1, o);
            }
            if (tig == 0) {
                s_sum[wn * 128 + lr0] = s0;  s_sq[wn * 128 + lr0] = q0;
                s_sum[wn * 128 + lr1] = s1;  s_sq[wn * 128 + lr1] = q1;
            }
        }
    }

    if (EPI == 2) {
        __syncthreads();
        #pragma unroll
        for (int mt = 0; mt < 4; mt++) {
            int lr0 = wm * 64 + mt * 16 + g;
            int lr1 = lr0 + 8;
            int p0 = permrow(mBase + lr0), p1 = permrow(mBase + lr1);
            float su0 = s_sum[lr0] + s_sum[128 + lr0] + s_sum[256 + lr0] + s_sum[384 + lr0];
            float sq0 = s_sq[lr0]  + s_sq[128 + lr0]  + s_sq[256 + lr0]  + s_sq[384 + lr0];
            float su1 = s_sum[lr1] + s_sum[128 + lr1] + s_sum[256 + lr1] + s_sum[384 + lr1];
            float sq1 = s_sq[lr1]  + s_sq[128 + lr1]  + s_sq[256 + lr1]  + s_sq[384 + lr1];
            float mu0 = su0 * (1.0f / Cdim);
            float mu1 = su1 * (1.0f / Cdim);
            float iv0 = rsqrtf(sq0 * (1.0f / Cdim) - mu0 * mu0 + 1e-5f);
            float iv1 = rsqrtf(sq1 * (1.0f / Cdim) - mu1 * mu1 + 1e-5f);
            #pragma unroll
            for (int nt = 0; nt < NT; nt++) {
                int c = wn * NT * 8 + nt * 8 + 2 * tig;
                float2 gv = *(const float2*)(g2 + c);
                float2 bb = *(const float2*)(b2v + c);
                float o0 = (acc[mt][nt][0] - mu0) * iv0 * gv.x + bb.x;
                float o1 = (acc[mt][nt][1] - mu0) * iv0 * gv.y + bb.y;
                float o2 = (acc[mt][nt][2] - mu1) * iv1 * gv.x + bb.x;
                float o3 = (acc[mt][nt][3] - mu1) * iv1 * gv.y + bb.y;
                *(bf162*)(C2 + (size_t)p0 * Cdim + c) = __floats2bfloat162_rn(o0, o1);
                *(bf162*)(C2 + (size_t)p1 * Cdim + c) = __floats2bfloat162_rn(o2, o3);
            }
        }
    }
}

// ------------------- register-resident flash attention ---------------------
// grid (NWIN, 3): one block per (window, head-pair); 8 warps = 2 heads x 4 rows.
__global__ __launch_bounds__(256)
void attn_kernel(const float* __restrict__ rpb_table) {
    __shared__ __align__(16) bf16 Qs[2][64][40];
    __shared__ __align__(16) bf16 Ks[2][64][40];
    __shared__ __align__(16) bf16 Vt[2][32][72];   // [head][d][token]
    __shared__ float rpbs[2][169];
    __shared__ int   gidm[64];

    int win = blockIdx.x;
    int h0  = blockIdx.y * 2;
    int tid = threadIdx.x;
    int wid = tid >> 5, lane = tid & 31;
    int g = lane >> 2, tig = lane & 3;
    int hsel = wid >> 2, wm2 = wid & 3;
    int wi = win & 63;
    int wh = wi >> 3, ww = wi & 7;

    if (tid < 64) {
        int v = -1;
        if (tid < 49) {
            int ri = tid / 7, ci = tid - ri * 7;
            int hi = wh * 7 + ri, wc = ww * 7 + ci;
            v = (hi < 49 ? 0 : (hi < 53 ? 1 : 2)) * 3 + (wc < 49 ? 0 : (wc < 53 ? 1 : 2));
        }
        gidm[tid] = v;
    }
    // zero V token-pad region (tokens 49..63)
    for (int idx = tid; idx < 2 * 32 * 15; idx += 256) {
        int hh = idx / 480, rem = idx - hh * 480;
        int d = rem / 15, n = 49 + rem - (rem / 15) * 15;
        Vt[hh][d][n] = __float2bfloat16(0.f);
    }

    const bf16* base = g_qkvb + (size_t)win * NTOK * 576;

    // rpb rows for both heads
    for (int idx = tid; idx < 338; idx += 256) {
        int hh = idx / 169, e = idx - hh * 169;
        rpbs[hh][e] = rpb_table[e * NHEADS + h0 + hh];
    }
    // Q, K: 49 tokens x (2 heads x 2 mats x 4 chunks)
    for (int idx = tid; idx < 784; idx += 256) {
        int n = idx >> 4, sub = idx & 15;
        int hh = sub >> 3, mat = (sub >> 2) & 1, ch = sub & 3;
        uint4 v = *(const uint4*)(base + (size_t)n * 576 + mat * 192 + (h0 + hh) * 32 + ch * 8);
        *(uint4*)(&(mat ? Ks : Qs)[hh][n][ch * 8]) = v;
    }
    // V transposed
    for (int idx = tid; idx < 392; idx += 256) {
        int n = idx >> 3, hh = (idx >> 2) & 1, ch = idx & 3;
        uint4 v = *(const uint4*)(base + (size_t)n * 576 + 384 + (h0 + hh) * 32 + ch * 8);
        bf16 tmp[8]; *(uint4*)tmp = v;
        #pragma unroll
        for (int e = 0; e < 8; e++) Vt[hh][ch * 8 + e][n] = tmp[e];
    }
    __syncthreads();

    // ---- S = Q K^T : this warp covers rows {r0, r0+8} x all 64 cols ----
    int r0 = wm2 * 16 + g, r1 = r0 + 8;
    float sf[8][4];
    #pragma unroll
    for (int j = 0; j < 8; j++)
        #pragma unroll
        for (int e = 0; e < 4; e++) sf[j][e] = 0.f;

    #pragma unroll
    for (int s = 0; s < 2; s++) {
        uint32_t a[4];
        const bf16* p0 = &Qs[hsel][r0][s * 16 + 2 * tig];
        a[0] = *(const uint32_t*)p0;
        a[1] = *(const uint32_t*)(p0 + 8 * 40);
        a[2] = *(const uint32_t*)(p0 + 8);
        a[3] = *(const uint32_t*)(p0 + 8 * 40 + 8);
        #pragma unroll
        for (int j = 0; j < 8; j++) {
            uint32_t b[2];
            const bf16* p = &Ks[hsel][j * 8 + g][s * 16 + 2 * tig];
            b[0] = *(const uint32_t*)p;
            b[1] = *(const uint32_t*)(p + 8);
            mma_bf16(sf[j], a, b);
        }
    }

    // ---- scale + rpb + shift-mask (rows/cols >= 49 -> -1e30) ----
    int gid0 = gidm[r0];
    int gid1 = gidm[r1];
    int ri0 = r0 / 7, ci0 = r0 - ri0 * 7;
    int ri1 = r1 / 7, ci1 = r1 - ri1 * 7;
    #pragma unroll
    for (int j = 0; j < 8; j++) {
        int c0 = j * 8 + 2 * tig;
        #pragma unroll
        for (int e = 0; e < 4; e++) {
            int r  = (e < 2) ? r0 : r1;
            int gid = (e < 2) ? gid0 : gid1;
            int ri = (e < 2) ? ri0 : ri1, ci = (e < 2) ? ci0 : ci1;
            int c = c0 + (e & 1);
            float v;
            if (r < 49 && c < 49) {
                int rj = c / 7, cj = c - rj * 7;
                v = sf[j][e] * SCALE + rpbs[hsel][(ri - rj + 6) * 13 + (ci - cj + 6)];
                if (gid != gidm[c]) v -= 100.f;
            } else {
                v = -1e30f;
            }
            sf[j][e] = v;
        }
    }

    // ---- softmax in registers (reduce across quad: shfl 1,2) ----
    float m0 = -1e30f, m1 = -1e30f;
    #pragma unroll
    for (int j = 0; j < 8; j++) {
        m0 = fmaxf(m0, fmaxf(sf[j][0], sf[j][1]));
        m1 = fmaxf(m1, fmaxf(sf[j][2], sf[j][3]));
    }
    m0 = fmaxf(m0, __shfl_xor_sync(0xffffffffu, m0, 1));
    m0 = fmaxf(m0, __shfl_xor_sync(0xffffffffu, m0, 2));
    m1 = fmaxf(m1, __shfl_xor_sync(0xffffffffu, m1, 1));
    m1 = fmaxf(m1, __shfl_xor_sync(0xffffffffu, m1, 2));
    float s0 = 0.f, s1 = 0.f;
    #pragma unroll
    for (int j = 0; j < 8; j++) {
        sf[j][0] = __expf(sf[j][0] - m0); s0 += sf[j][0];
        sf[j][1] = __expf(sf[j][1] - m0); s0 += sf[j][1];
        sf[j][2] = __expf(sf[j][2] - m1); s1 += sf[j][2];
        sf[j][3] = __expf(sf[j][3] - m1); s1 += sf[j][3];
    }
    s0 += __shfl_xor_sync(0xffffffffu, s0, 1);
    s0 += __shfl_xor_sync(0xffffffffu, s0, 2);
    s1 += __shfl_xor_sync(0xffffffffu, s1, 1);
    s1 += __shfl_xor_sync(0xffffffffu, s1, 2);
    float inv0 = __fdividef(1.0f, s0);
    float inv1 = __fdividef(1.0f, s1);

    // ---- pack P into A fragments directly from accumulators ----
    uint32_t pa[4][4];
    #pragma unroll
    for (int ks = 0; ks < 4; ks++) {
        pa[ks][0] = pack_bf162(sf[2 * ks][0] * inv0, sf[2 * ks][1] * inv0);
        pa[ks][1] = pack_bf162(sf[2 * ks][2] * inv1, sf[2 * ks][3] * inv1);
        pa[ks][2] = pack_bf162(sf[2 * ks + 1][0] * inv0, sf[2 * ks + 1][1] * inv0);
        pa[ks][3] = pack_bf162(sf[2 * ks + 1][2] * inv1, sf[2 * ks + 1][3] * inv1);
    }

    // ---- O = P V ----
    float of[4][4];
    #pragma unroll
    for (int t = 0; t < 4; t++)
        #pragma unroll
        for (int e = 0; e < 4; e++) of[t][e] = 0.f;
    #pragma unroll
    for (int ks = 0; ks < 4; ks++) {
        #pragma unroll
        for (int t = 0; t < 4; t++) {
            uint32_t b[2];
            const bf16* p = &Vt[hsel][t * 8 + g][ks * 16 + 2 * tig];
            b[0] = *(const uint32_t*)p;
            b[1] = *(const uint32_t*)(p + 8);
            mma_bf16(of[t], pa[ks], b);
        }
    }

    // ---- store O ----
    int h = h0 + hsel;
    #pragma unroll
    for (int t = 0; t < 4; t++) {
        int c = t * 8 + 2 * tig;
        if (r0 < 49) {
            bf16* o = g_attnob + (size_t)(win * NTOK + r0) * Cdim + h * HDIM + c;
            *(bf162*)o = __floats2bfloat162_rn(of[t][0], of[t][1]);
        }
        if (r1 < 49) {
            bf16* o = g_attnob + (size_t)(win * NTOK + r1) * Cdim + h * HDIM + c;
            *(bf162*)o = __floats2bfloat162_rn(of[t][2], of[t][3]);
        }
    }
}

// ------------------------------ launcher -----------------------------------
#define SM3 (2 * (128 + 96) * SROW * 2)                    // 64512 B
#define SM6 (2 * (128 + 192) * SROW * 2 + 4096)            // 96256 B

extern "C" void kernel_launch(void* const* d_in, const int* in_sizes, int n_in,
                              void* d_out, int out_size) {
    const float* x      = (const float*)d_in[0];
    const float* qkv_w  = (const float*)d_in[1];
    const float* qkv_b  = (const float*)d_in[2];
    const float* proj_w = (const float*)d_in[3];
    const float* proj_b = (const float*)d_in[4];
    const float* rpb    = (const float*)d_in[5];
    const float* ln1_g  = (const float*)d_in[6];
    const float* ln1_b  = (const float*)d_in[7];
    const float* ln2_g  = (const float*)d_in[8];
    const float* ln2_b  = (const float*)d_in[9];
    const float* w1     = (const float*)d_in[10];
    const float* b1     = (const float*)d_in[11];
    const float* w2     = (const float*)d_in[12];
    const float* b2     = (const float*)d_in[13];
    float* out = (float*)d_out;

    bf16 *p_win, *p_qkv, *p_attno, *p_ln2, *p_hid;
    bf16 *p_qkvwT, *p_projwT, *p_w1T, *p_w2T;
    float *p_h;
    cudaGetSymbolAddress((void**)&p_win,    g_winb);
    cudaGetSymbolAddress((void**)&p_qkv,    g_qkvb);
    cudaGetSymbolAddress((void**)&p_attno,  g_attnob);
    cudaGetSymbolAddress((void**)&p_h,      g_h);
    cudaGetSymbolAddress((void**)&p_ln2,    g_ln2b);
    cudaGetSymbolAddress((void**)&p_hid,    g_hidb);
    cudaGetSymbolAddress((void**)&p_qkvwT,  g_qkvwT);
    cudaGetSymbolAddress((void**)&p_projwT, g_projwT);
    cudaGetSymbolAddress((void**)&p_w1T,    g_w1T);
    cudaGetSymbolAddress((void**)&p_w2T,    g_w2T);

    cudaFuncSetAttribute(tc_gemm<0,3,true>,  cudaFuncAttributeMaxDynamicSharedMemorySize, SM3);
    cudaFuncSetAttribute(tc_gemm<1,3,true>,  cudaFuncAttributeMaxDynamicSharedMemorySize, SM3);
    cudaFuncSetAttribute(tc_gemm<2,6,false>, cudaFuncAttributeMaxDynamicSharedMemorySize, SM6);
    cudaFuncSetAttribute(tc_gemm<3,3,false>, cudaFuncAttributeMaxDynamicSharedMemorySize, SM3);

    // 0. all weight transposes (fp32 -> bf16, K-major)
    transpose_all<<<dim3(24, 24, 4), dim3(32, 8)>>>(qkv_w, proj_w, w1, w2,
                                                    p_qkvwT, p_projwT, p_w1T, p_w2T);

    // 1. LN1 + shifted-window partition -> bf16
    ln_kernel<<<MROWS / 8, 256>>>(x, ln1_g, ln1_b, p_win);

    // 2. QKV: (100352,192) @ (192,576) -> bf16
    tc_gemm<0,3,true><<<dim3(MROWS / 128, 6), 256, SM3>>>(
        p_win, p_qkvwT, qkv_b, p_qkv, 576, 192, nullptr, nullptr, nullptr, nullptr);

    // 3. windowed attention (register flash; grid = window x head-pair)
    attn_kernel<<<dim3(NWIN, 3), 256>>>(rpb);

    // 4. proj + window-reverse + residual(x) + fused LN2 (g_h fp32, g_ln2 bf16)
    tc_gemm<2,6,false><<<dim3(MROWS / 128, 1), 256, SM6>>>(
        p_attno, p_projwT, proj_b, p_h, 192, 192, x, p_ln2, ln2_g, ln2_b);

    // 5. MLP1 + GELU -> bf16
    tc_gemm<1,3,true><<<dim3(MROWS / 128, 8), 256, SM3>>>(
        p_ln2, p_w1T, b1, p_hid, HID, 192, nullptr, nullptr, nullptr, nullptr);

    // 6. MLP2 + residual(h) -> fp32 out
    tc_gemm<3,3,false><<<dim3(MROWS / 128, 2), 256, SM3>>>(
        p_hid, p_w2T, b2, out, 192, HID, p_h, nullptr, nullptr, nullptr);
}